// round 13
// baseline (speedup 1.0000x reference)
#include <cuda_runtime.h>
#include <cuda_bf16.h>
#include <math.h>
#include <stdint.h>

// ---------------------------------------------------------------------------
// Problem constants
// ---------------------------------------------------------------------------
#define BB      2
#define II      2048
#define JJ      16
#define NKK     2048
#define DMODEL  256
#define DHIDDEN 512
#define HH      8
#define DK      64

#define ROWS_BI   (BB * II)            // 4096
#define ROWS_BIJ  (BB * II * JJ)       // 65536

#define KCAT (DHIDDEN + HH * DHIDDEN)  // 4608

// ---------------------------------------------------------------------------
// Scratch (device globals — no allocation allowed)
// ---------------------------------------------------------------------------
__device__ __nv_bfloat16 g_qs_hi[ROWS_BI * DMODEL];
__device__ __nv_bfloat16 g_qs_lo[ROWS_BI * DMODEL];
__device__ __nv_bfloat16 g_ks_hi[ROWS_BI * DMODEL];
__device__ __nv_bfloat16 g_ks_lo[ROWS_BI * DMODEL];
__device__ __nv_bfloat16 g_ps_hi[(size_t)ROWS_BIJ * DHIDDEN];   // 64 MB
__device__ __nv_bfloat16 g_ps_lo[(size_t)ROWS_BIJ * DHIDDEN];   // 64 MB

__device__ __nv_bfloat16 g_qh2_hi[ROWS_BI * DHIDDEN];
__device__ __nv_bfloat16 g_qh2_lo[ROWS_BI * DHIDDEN];
__device__ __nv_bfloat16 g_w2s_hi[DHIDDEN * 2 * DHIDDEN];
__device__ __nv_bfloat16 g_w2s_lo[DHIDDEN * 2 * DHIDDEN];

// combined attention output: [4096, 4608]  (akv | hbar)
__device__ __nv_bfloat16 g_aout_hi[(size_t)ROWS_BI * KCAT];   // 37.7 MB
__device__ __nv_bfloat16 g_aout_lo[(size_t)ROWS_BI * KCAT];   // 37.7 MB

// transposed split weights (q/kv/W1 paths)
#define WQ_OFF   0
#define WQ_SZ    (DHIDDEN * DMODEL)
#define WKV_OFF  (WQ_OFF + WQ_SZ)
#define WKV_SZ   (2 * DHIDDEN * DMODEL)
#define W1_OFF   (WKV_OFF + WKV_SZ)
#define W1_SZ    (DHIDDEN * DHIDDEN)
#define WT_TOTAL (W1_OFF + W1_SZ)

__device__ __nv_bfloat16 g_wt_hi[WT_TOTAL];
__device__ __nv_bfloat16 g_wt_lo[WT_TOTAL];

// concatenated output weight [256, 4608]: [0,512)=WoutT, [512,4608)=WfoldT
__device__ __nv_bfloat16 g_wcat_hi[DMODEL * KCAT];
__device__ __nv_bfloat16 g_wcat_lo[DMODEL * KCAT];

__device__ float g_qh[ROWS_BI * DHIDDEN];
__device__ float g_kv[ROWS_BI * 2 * DHIDDEN];
__device__ float g_hidden[(size_t)ROWS_BIJ * DHIDDEN];     // 128 MB fp32
__device__ float g_wtilde[(size_t)ROWS_BI * HH * DHIDDEN]; // 64 MB fp32
__device__ float g_wfold[HH * DHIDDEN * DMODEL];           // 4 MB fp32
__device__ float g_bfold[DMODEL];
__device__ int   g_idx_is64;

// ---------------------------------------------------------------------------
// local_idx dtype detection
// ---------------------------------------------------------------------------
__global__ void detect_idx_kernel(const void* idx_raw) {
    if (threadIdx.x == 0 && blockIdx.x == 0) {
        const long long* p = (const long long*)idx_raw;
        int is64 = 1;
        for (int s = 0; s < 64; s++) {
            long long v = p[s * 37];
            if (v < 0 || v >= NKK) { is64 = 0; break; }
        }
        g_idx_is64 = is64;
    }
}

// ---------------------------------------------------------------------------
// fp32 -> (bf16 hi, bf16 lo) split, vectorized by 4
// ---------------------------------------------------------------------------
__global__ void split_kernel(const float* __restrict__ x,
                             __nv_bfloat16* __restrict__ hi,
                             __nv_bfloat16* __restrict__ lo, size_t n4)
{
    size_t i = ((size_t)blockIdx.x * blockDim.x + threadIdx.x);
    if (i >= n4) return;
    float4 v = ((const float4*)x)[i];
    __nv_bfloat16 h0 = __float2bfloat16(v.x);
    __nv_bfloat16 h1 = __float2bfloat16(v.y);
    __nv_bfloat16 h2 = __float2bfloat16(v.z);
    __nv_bfloat16 h3 = __float2bfloat16(v.w);
    __nv_bfloat16 l0 = __float2bfloat16(v.x - __bfloat162float(h0));
    __nv_bfloat16 l1 = __float2bfloat16(v.y - __bfloat162float(h1));
    __nv_bfloat16 l2 = __float2bfloat16(v.z - __bfloat162float(h2));
    __nv_bfloat16 l3 = __float2bfloat16(v.w - __bfloat162float(h3));
    __nv_bfloat162* hp = (__nv_bfloat162*)(hi + i * 4);
    __nv_bfloat162* lp = (__nv_bfloat162*)(lo + i * 4);
    hp[0] = __nv_bfloat162(h0, h1); hp[1] = __nv_bfloat162(h2, h3);
    lp[0] = __nv_bfloat162(l0, l1); lp[1] = __nv_bfloat162(l2, l3);
}

// split + transpose weights: W[K,N] -> Wt_hi/lo[N, out_ld] at column out_off
__global__ void splitT_kernel(const float* __restrict__ W,
                              __nv_bfloat16* __restrict__ thi,
                              __nv_bfloat16* __restrict__ tlo,
                              int K, int N, int out_ld, int out_off)
{
    int idx = blockIdx.x * 256 + threadIdx.x;
    if (idx >= K * N) return;
    int k = idx / N, n = idx % N;
    float v = W[idx];
    __nv_bfloat16 h = __float2bfloat16(v);
    __nv_bfloat16 l = __float2bfloat16(v - __bfloat162float(h));
    thi[(size_t)n * out_ld + out_off + k] = h;
    tlo[(size_t)n * out_ld + out_off + k] = l;
}

// ---------------------------------------------------------------------------
// Wfold[(h*512+c), m] = sum_d W2[c, h*128+64+d] * Wout[h*64+d, m]
// bfold[m] = sum_{h,d} b2[h*128+64+d] * Wout[h*64+d, m]
// ---------------------------------------------------------------------------
__global__ void prep_fold_kernel(const float* __restrict__ W2,
                                 const float* __restrict__ Wout,
                                 float* __restrict__ Wfold)
{
    const int hc = blockIdx.x;
    const int h = hc >> 9, c = hc & 511;
    __shared__ float w2s[64];
    if (threadIdx.x < 64)
        w2s[threadIdx.x] = W2[c * 1024 + h * 128 + 64 + threadIdx.x];
    __syncthreads();
    const int m = threadIdx.x;
    float a = 0.0f;
    #pragma unroll 8
    for (int d = 0; d < 64; d++)
        a = fmaf(w2s[d], Wout[(h * 64 + d) * 256 + m], a);
    Wfold[(size_t)hc * 256 + m] = a;
}

__global__ void prep_bfold_kernel(const float* __restrict__ b2,
                                  const float* __restrict__ Wout,
                                  float* __restrict__ bfold)
{
    const int m = threadIdx.x;
    float a = 0.0f;
    for (int h = 0; h < 8; h++)
        for (int d = 0; d < 64; d++)
            a = fmaf(b2[h * 128 + 64 + d], Wout[(h * 64 + d) * 256 + m], a);
    bfold[m] = a;
}

// ---------------------------------------------------------------------------
// mma.sync helpers
// ---------------------------------------------------------------------------
__device__ __forceinline__ uint32_t smem_u32(const void* p) {
    uint32_t a;
    asm("{ .reg .u64 t; cvta.to.shared.u64 t, %1; cvt.u32.u64 %0, t; }"
        : "=r"(a) : "l"(p));
    return a;
}

#define SW128(o) ((o) ^ (((o) >> 3) & 0x70))

__device__ __forceinline__ void cp_async16(uint32_t saddr, const void* gaddr) {
    asm volatile("cp.async.cg.shared.global [%0], [%1], 16;"
                 :: "r"(saddr), "l"(gaddr));
}
__device__ __forceinline__ void ldsm_x4(uint32_t& a0, uint32_t& a1,
                                        uint32_t& a2, uint32_t& a3, uint32_t addr) {
    asm volatile("ldmatrix.sync.aligned.m8n8.x4.shared.b16 {%0,%1,%2,%3}, [%4];"
                 : "=r"(a0), "=r"(a1), "=r"(a2), "=r"(a3) : "r"(addr));
}
__device__ __forceinline__ void mma16816(float* c, const uint32_t* a,
                                         uint32_t b0, uint32_t b1) {
    asm volatile(
        "mma.sync.aligned.m16n8k16.row.col.f32.bf16.bf16.f32 "
        "{%0,%1,%2,%3}, {%4,%5,%6,%7}, {%8,%9}, {%0,%1,%2,%3};"
        : "+f"(c[0]), "+f"(c[1]), "+f"(c[2]), "+f"(c[3])
        : "r"(a[0]), "r"(a[1]), "r"(a[2]), "r"(a[3]), "r"(b0), "r"(b1));
}

// ---------------------------------------------------------------------------
// Tensor-core GEMM via mma.sync (split bf16, 3-term) — exact R9 configuration
// (2-stage, measured best). C[ROWS x NT tile] = A[M,K](lda) @ Wt[N,K](ldb)^T
// ---------------------------------------------------------------------------
#define FL_F32   1
#define FL_SPLIT 2
#define FL_RELU  4

template<int WGM, int WGN, int MI, int NI, int OCC>
__global__ __launch_bounds__(256, OCC) void tgemm_kernel(
    const __nv_bfloat16* __restrict__ Ahi, const __nv_bfloat16* __restrict__ Alo,
    int lda, size_t a_zs,
    const __nv_bfloat16* __restrict__ Bhi, const __nv_bfloat16* __restrict__ Blo,
    int ldb, size_t b_zs,
    const float* __restrict__ bias,
    float* __restrict__ Cf,
    __nv_bfloat16* __restrict__ Chi, __nv_bfloat16* __restrict__ Clo,
    int ldc, size_t c_zs,
    int K, int flags)
{
    static_assert(NI % 2 == 0, "NI must be even for x4 B loads");
    constexpr int ROWS    = WGM * MI * 16;
    constexpr int NT      = WGN * NI * 8;
    constexpr int A_BYTES = ROWS * 128;            // per hi / per lo
    constexpr int B_BYTES = NT * 128;
    constexpr int SB_HI   = 2 * A_BYTES;
    constexpr int SB_LO   = 2 * A_BYTES + B_BYTES;
    constexpr int STB     = 2 * A_BYTES + 2 * B_BYTES;   // stage bytes
    constexpr int BS      = NT + 4;                // epilogue buf stride

    extern __shared__ char smem_raw[];
    uint32_t base0 = smem_u32(smem_raw);
    uint32_t base  = (base0 + 1023) & ~1023u;
    char*    smem  = smem_raw + (base - base0);

    const int tid  = threadIdx.x;
    const int warp = tid >> 5, lane = tid & 31;
    const int wm = warp / WGN, wn = warp % WGN;
    const int rowA0 = blockIdx.y * ROWS;
    const int rowB0 = blockIdx.x * NT;
    const size_t z = blockIdx.z;

    const __nv_bfloat16* AhiZ = Ahi + z * a_zs;
    const __nv_bfloat16* AloZ = Alo + z * a_zs;
    const __nv_bfloat16* BhiZ = Bhi + z * b_zs;
    const __nv_bfloat16* BloZ = Blo + z * b_zs;

    float acc[MI][NI][4];
    #pragma unroll
    for (int mi = 0; mi < MI; mi++)
        #pragma unroll
        for (int ni = 0; ni < NI; ni++)
            #pragma unroll
            for (int r = 0; r < 4; r++) acc[mi][ni][r] = 0.0f;

    const int nchunks = K >> 6;

    auto load_chunk = [&](int chunk, int stage) {
        const int k0 = chunk << 6;
        uint32_t st = base + stage * STB;
        #pragma unroll
        for (int l = 0; l < ROWS * 8 / 256; l++) {
            int id = tid + (l << 8);
            int r = id >> 3, c = id & 7;
            uint32_t so = SW128((uint32_t)(r * 128 + c * 16));
            size_t ga = (size_t)(rowA0 + r) * lda + k0 + (c << 3);
            cp_async16(st + so, AhiZ + ga);
            cp_async16(st + A_BYTES + so, AloZ + ga);
        }
        #pragma unroll
        for (int l = 0; l < NT * 8 / 256; l++) {
            int id = tid + (l << 8);
            int r = id >> 3, c = id & 7;
            uint32_t so = SW128((uint32_t)(r * 128 + c * 16));
            size_t gb = (size_t)(rowB0 + r) * ldb + k0 + (c << 3);
            cp_async16(st + SB_HI + so, BhiZ + gb);
            cp_async16(st + SB_LO + so, BloZ + gb);
        }
        asm volatile("cp.async.commit_group;");
    };

    const int a_row_l = wm * (MI * 16) + (lane & 15);
    const int a_cb_l  = (lane >> 4) << 4;
    const int b_row_l = wn * (NI * 8) + (lane & 7) + ((lane >> 4) << 3);
    const int b_cb_l  = ((lane >> 3) & 1) << 4;

    load_chunk(0, 0);

    for (int i = 0; i < nchunks; i++) {
        const int s = i & 1;
        if (i + 1 < nchunks) {
            load_chunk(i + 1, 1 - s);
            asm volatile("cp.async.wait_group 1;");
        } else {
            asm volatile("cp.async.wait_group 0;");
        }
        __syncthreads();

        const uint32_t st = base + s * STB;
        #pragma unroll
        for (int ks = 0; ks < 4; ks++) {
            const int kb = ks << 5;
            uint32_t ah[MI][4], al[MI][4], bh[NI][2], bl[NI][2];
            #pragma unroll
            for (int mi = 0; mi < MI; mi++) {
                uint32_t so = SW128((uint32_t)((a_row_l + mi * 16) * 128 + kb + a_cb_l));
                ldsm_x4(ah[mi][0], ah[mi][1], ah[mi][2], ah[mi][3], st + so);
                ldsm_x4(al[mi][0], al[mi][1], al[mi][2], al[mi][3], st + A_BYTES + so);
            }
            #pragma unroll
            for (int p = 0; p < NI / 2; p++) {
                uint32_t off = SW128((uint32_t)((b_row_l + p * 16) * 128 + kb + b_cb_l));
                ldsm_x4(bh[2 * p][0], bh[2 * p][1], bh[2 * p + 1][0], bh[2 * p + 1][1],
                        st + SB_HI + off);
                ldsm_x4(bl[2 * p][0], bl[2 * p][1], bl[2 * p + 1][0], bl[2 * p + 1][1],
                        st + SB_LO + off);
            }
            #pragma unroll
            for (int ni = 0; ni < NI; ni++)
                #pragma unroll
                for (int mi = 0; mi < MI; mi++) {
                    mma16816(acc[mi][ni], ah[mi], bh[ni][0], bh[ni][1]);
                    mma16816(acc[mi][ni], ah[mi], bl[ni][0], bl[ni][1]);
                    mma16816(acc[mi][ni], al[mi], bh[ni][0], bh[ni][1]);
                }
        }
        __syncthreads();
    }

    // ---- epilogue: regs -> SMEM bounce (stride BS f32) -> global
    float* buf = (float*)smem;
    {
        const int r0 = wm * (MI * 16) + (lane >> 2);
        const int c0 = wn * (NI * 8) + ((lane & 3) << 1);
        #pragma unroll
        for (int mi = 0; mi < MI; mi++)
            #pragma unroll
            for (int ni = 0; ni < NI; ni++) {
                int rr = r0 + mi * 16;
                int cc = c0 + ni * 8;
                buf[rr * BS + cc]           = acc[mi][ni][0];
                buf[rr * BS + cc + 1]       = acc[mi][ni][1];
                buf[(rr + 8) * BS + cc]     = acc[mi][ni][2];
                buf[(rr + 8) * BS + cc + 1] = acc[mi][ni][3];
            }
    }
    __syncthreads();

    {
        constexpr int TPR = 256 / ROWS;         // threads per row
        constexpr int CPT = NT / TPR;           // cols per thread
        const int rloc = tid / TPR;
        const int colb = (tid % TPR) * CPT;
        const size_t grow = (size_t)(rowA0 + rloc);
        float vals[CPT];
        #pragma unroll
        for (int c = 0; c < CPT; c++) {
            float v = buf[rloc * BS + colb + c];
            if (bias) v += bias[rowB0 + colb + c];
            if (flags & FL_RELU) v = fmaxf(v, 0.0f);
            vals[c] = v;
        }
        if (flags & FL_F32) {
            float* crow = Cf + z * c_zs + grow * ldc + rowB0 + colb;
            #pragma unroll
            for (int c = 0; c < CPT; c += 4) {
                float4 o = {vals[c], vals[c + 1], vals[c + 2], vals[c + 3]};
                *(float4*)(crow + c) = o;
            }
        }
        if (flags & FL_SPLIT) {
            __nv_bfloat16* hrow = Chi + z * c_zs + grow * ldc + rowB0 + colb;
            __nv_bfloat16* lrow = Clo + z * c_zs + grow * ldc + rowB0 + colb;
            #pragma unroll
            for (int c = 0; c < CPT; c += 8) {
                __nv_bfloat16 hv[8], lv[8];
                #pragma unroll
                for (int u = 0; u < 8; u++) {
                    float v = vals[c + u];
                    hv[u] = __float2bfloat16(v);
                    lv[u] = __float2bfloat16(v - __bfloat162float(hv[u]));
                }
                *(uint4*)(hrow + c) = *(uint4*)hv;
                *(uint4*)(lrow + c) = *(uint4*)lv;
            }
        }
    }
}

// variants: BIG 128x128 (occ1), SLIM 128x64 (occ2), OUT 64x64 (occ3) — R9 exact
#define TG_BIG  tgemm_kernel<2, 4, 4, 4, 1>
#define TG_SLIM tgemm_kernel<4, 2, 2, 4, 2>
#define TG_OUT  tgemm_kernel<2, 4, 2, 2, 3>
#define SMEM_BIG  (1024 + 2 * (2 * 128 * 128 + 2 * 128 * 128))   // 132096
#define SMEM_SLIM (1024 + 2 * (2 * 128 * 128 + 2 * 64 * 128))    // 99328
#define SMEM_OUT  (1024 + 2 * (2 * 64 * 128 + 2 * 64 * 128))     // 66560

// ---------------------------------------------------------------------------
// Fused attention v2 (R12): register-reuse logits + loop-swapped hbar.
// row = row0 + blockIdx.x for half launches.
// ---------------------------------------------------------------------------
#define HS 516              // hid row stride (floats)
#define WS 516              // wt row stride
#define QS 68               // qvp row stride
#define PS_ 132             // part cb stride
#define SM_QV   0
#define SM_WT   (8 * QS)                    // 544
#define SM_HID  (SM_WT + 8 * WS)            // 4672
#define SM_VV   (SM_HID + 16 * HS)          // 12928
#define SM_PART (SM_VV + 16 * 512)          // 21120
#define AT_FLOATS (SM_PART + 16 * PS_ + 16)
#define AT_SMEM (AT_FLOATS * 4)

__global__ __launch_bounds__(256) void attn_fused_kernel(
    const float* __restrict__ qh, const float* __restrict__ kvb,
    const float* __restrict__ hidden, const float* __restrict__ wtilde,
    const void* __restrict__ idx_raw,
    __nv_bfloat16* __restrict__ aout_hi, __nv_bfloat16* __restrict__ aout_lo,
    int row0)
{
    extern __shared__ float sm[];
    float* qvp  = sm + SM_QV;
    float* wt   = sm + SM_WT;
    float* hid  = sm + SM_HID;
    float* vv   = sm + SM_VV;
    float* part = sm + SM_PART;
    __shared__ int   sidx[JJ];
    __shared__ float lg[JJ][HH];
    __shared__ __align__(16) float aw[JJ][HH];

    const int row = row0 + blockIdx.x;
    const int b   = row >> 11;
    const int t   = threadIdx.x;

    if (t < JJ) {
        long long n;
        if (g_idx_is64) n = ((const long long*)idx_raw)[(size_t)row * JJ + t];
        else            n = ((const int*)idx_raw)[(size_t)row * JJ + t];
        sidx[t] = b * NKK + (int)n;
    }
    #pragma unroll
    for (int rep = 0; rep < 2; rep++) {
        int o = t + (rep << 8);
        qvp[(o >> 6) * QS + (o & 63)] = qh[(size_t)row * 512 + o];
    }
    {
        const float4* wsrc = (const float4*)(wtilde + (size_t)row * 4096);
        #pragma unroll
        for (int l = 0; l < 4; l++) {
            int i4 = t + (l << 8);
            int h = i4 >> 7, c = (i4 & 127) << 2;
            *(float4*)(wt + h * WS + c) = wsrc[i4];
        }
        const float4* hsrc = (const float4*)(hidden + (size_t)row * JJ * 512);
        #pragma unroll
        for (int l = 0; l < 8; l++) {
            int i4 = t + (l << 8);
            int j = i4 >> 7, c = (i4 & 127) << 2;
            *(float4*)(hid + j * HS + c) = hsrc[i4];
        }
    }
    __syncthreads();
    #pragma unroll
    for (int j = 0; j < JJ; j++) {
        const float2* vp = (const float2*)(kvb + (size_t)sidx[j] * 1024 + 512);
        ((float2*)(vv + j * 512))[t] = vp[t];
    }

    // ---- logits partials: thread = (cb, j); 32 hid floats cached in regs
    {
        const int cb = t >> 4;          // 0..15
        const int j  = t & 15;
        float h32[32];
        const float* hrow = hid + j * HS + cb * 32;
        #pragma unroll
        for (int i = 0; i < 32; i += 4) {
            float4 v = *(const float4*)(hrow + i);
            h32[i] = v.x; h32[i + 1] = v.y; h32[i + 2] = v.z; h32[i + 3] = v.w;
        }
        const int stag = (cb & 1) << 4;
        #pragma unroll
        for (int h = 0; h < 8; h++) {
            const float* wrow = wt + h * WS + cb * 32;
            float p = 0.0f;
            #pragma unroll
            for (int ii = 0; ii < 32; ii++) {
                int i = (ii + stag) & 31;
                p = fmaf(h32[i], wrow[i], p);
            }
            part[cb * PS_ + j * 8 + h] = p;
        }
    }
    __syncthreads();

    // ---- reduce partials + q.k term
    if (t < JJ * HH) {
        const int j = t >> 3, h = t & 7;
        float s = 0.0f;
        #pragma unroll
        for (int cb = 0; cb < 16; cb++) s += part[cb * PS_ + j * 8 + h];
        const float* kp = kvb + (size_t)sidx[j] * 1024 + h * 64;
        const float* qp = qvp + h * QS;
        #pragma unroll
        for (int d = 0; d < 64; d += 4) {
            float4 k4 = *(const float4*)(kp + d);
            s = fmaf(qp[d + 0], k4.x, s);
            s = fmaf(qp[d + 1], k4.y, s);
            s = fmaf(qp[d + 2], k4.z, s);
            s = fmaf(qp[d + 3], k4.w, s);
        }
        lg[j][h] = s * 0.125f;
    }
    __syncthreads();

    if (t < HH) {
        float m = -1e30f;
        #pragma unroll
        for (int j = 0; j < JJ; j++) m = fmaxf(m, lg[j][t]);
        float ssum = 0.0f;
        #pragma unroll
        for (int j = 0; j < JJ; j++) {
            float e = expf(lg[j][t] - m);
            aw[j][t] = e;
            ssum += e;
        }
        float inv = 1.0f / ssum;
        #pragma unroll
        for (int j = 0; j < JJ; j++) aw[j][t] *= inv;
    }
    __syncthreads();

    // ---- akv
    #pragma unroll
    for (int rep = 0; rep < 2; rep++) {
        int o = t + (rep << 8);
        int h = o >> 6, d = o & 63;
        float a = 0.0f;
        #pragma unroll
        for (int j = 0; j < JJ; j++)
            a = fmaf(aw[j][h], vv[j * 512 + h * 64 + d], a);
        __nv_bfloat16 hv = __float2bfloat16(a);
        __nv_bfloat16 lv = __float2bfloat16(a - __bfloat162float(hv));
        aout_hi[(size_t)row * KCAT + o] = hv;
        aout_lo[(size_t)row * KCAT + o] = lv;
    }

    // ---- hbar loop-swapped
    {
        const int c0 = t << 1;
        float a2[8][2];
        #pragma unroll
        for (int h = 0; h < 8; h++) { a2[h][0] = 0.0f; a2[h][1] = 0.0f; }
        #pragma unroll
        for (int j = 0; j < JJ; j++) {
            float2 v = *(const float2*)(hid + j * HS + c0);
            float4 w0 = *(const float4*)(&aw[j][0]);
            float4 w1 = *(const float4*)(&aw[j][4]);
            a2[0][0] = fmaf(w0.x, v.x, a2[0][0]); a2[0][1] = fmaf(w0.x, v.y, a2[0][1]);
            a2[1][0] = fmaf(w0.y, v.x, a2[1][0]); a2[1][1] = fmaf(w0.y, v.y, a2[1][1]);
            a2[2][0] = fmaf(w0.z, v.x, a2[2][0]); a2[2][1] = fmaf(w0.z, v.y, a2[2][1]);
            a2[3][0] = fmaf(w0.w, v.x, a2[3][0]); a2[3][1] = fmaf(w0.w, v.y, a2[3][1]);
            a2[4][0] = fmaf(w1.x, v.x, a2[4][0]); a2[4][1] = fmaf(w1.x, v.y, a2[4][1]);
            a2[5][0] = fmaf(w1.y, v.x, a2[5][0]); a2[5][1] = fmaf(w1.y, v.y, a2[5][1]);
            a2[6][0] = fmaf(w1.z, v.x, a2[6][0]); a2[6][1] = fmaf(w1.z, v.y, a2[6][1]);
            a2[7][0] = fmaf(w1.w, v.x, a2[7][0]); a2[7][1] = fmaf(w1.w, v.y, a2[7][1]);
        }
        #pragma unroll
        for (int h = 0; h < 8; h++) {
            __nv_bfloat16 h0 = __float2bfloat16(a2[h][0]);
            __nv_bfloat16 h1 = __float2bfloat16(a2[h][1]);
            __nv_bfloat16 l0 = __float2bfloat16(a2[h][0] - __bfloat162float(h0));
            __nv_bfloat16 l1 = __float2bfloat16(a2[h][1] - __bfloat162float(h1));
            size_t ob = (size_t)row * KCAT + 512 + h * 512 + c0;
            *(__nv_bfloat162*)(aout_hi + ob) = __nv_bfloat162(h0, h1);
            *(__nv_bfloat162*)(aout_lo + ob) = __nv_bfloat162(l0, l1);
        }
    }
}

// ---------------------------------------------------------------------------
// Launch: R12 schedule + attn/out tail overlap (single new variable)
// inputs: 0:q 1:k 2:pos 3:local_idx 4:Wq 5:Wkv 6:W1 7:b1 8:W2 9:b2 10:Wout
// ---------------------------------------------------------------------------
extern "C" void kernel_launch(void* const* d_in, const int* in_sizes, int n_in,
                              void* d_out, int out_size)
{
    const float* q    = (const float*)d_in[0];
    const float* k    = (const float*)d_in[1];
    const float* pos  = (const float*)d_in[2];
    const void*  lidx = d_in[3];
    const float* Wq   = (const float*)d_in[4];
    const float* Wkv  = (const float*)d_in[5];
    const float* W1   = (const float*)d_in[6];
    const float* b1   = (const float*)d_in[7];
    const float* W2   = (const float*)d_in[8];
    const float* b2   = (const float*)d_in[9];
    const float* Wout = (const float*)d_in[10];
    float* out = (float*)d_out;

    static cudaStream_t s1 = nullptr, s2 = nullptr;
    static cudaEvent_t ev0, ev1, ev2, eva0, evo0;
    static int init_done = 0;
    if (!init_done) {
        cudaStreamCreateWithFlags(&s1, cudaStreamNonBlocking);
        cudaStreamCreateWithFlags(&s2, cudaStreamNonBlocking);
        cudaEventCreateWithFlags(&ev0, cudaEventDisableTiming);
        cudaEventCreateWithFlags(&ev1, cudaEventDisableTiming);
        cudaEventCreateWithFlags(&ev2, cudaEventDisableTiming);
        cudaEventCreateWithFlags(&eva0, cudaEventDisableTiming);
        cudaEventCreateWithFlags(&evo0, cudaEventDisableTiming);
        cudaFuncSetAttribute(TG_BIG,
                             cudaFuncAttributeMaxDynamicSharedMemorySize, SMEM_BIG);
        cudaFuncSetAttribute(TG_SLIM,
                             cudaFuncAttributeMaxDynamicSharedMemorySize, SMEM_SLIM);
        cudaFuncSetAttribute(TG_OUT,
                             cudaFuncAttributeMaxDynamicSharedMemorySize, SMEM_OUT);
        cudaFuncSetAttribute(attn_fused_kernel,
                             cudaFuncAttributeMaxDynamicSharedMemorySize, AT_SMEM);
        init_done = 1;
    }

    __nv_bfloat16 *qs_hi, *qs_lo, *ks_hi, *ks_lo, *ps_hi, *ps_lo;
    __nv_bfloat16 *qh2_hi, *qh2_lo, *w2s_hi, *w2s_lo;
    __nv_bfloat16 *aout_hi, *aout_lo, *wt_hi, *wt_lo, *wcat_hi, *wcat_lo;
    float *qh, *kv, *hidden, *wtilde, *wfold, *bfold;
    cudaGetSymbolAddress((void**)&qs_hi, g_qs_hi);
    cudaGetSymbolAddress((void**)&qs_lo, g_qs_lo);
    cudaGetSymbolAddress((void**)&ks_hi, g_ks_hi);
    cudaGetSymbolAddress((void**)&ks_lo, g_ks_lo);
    cudaGetSymbolAddress((void**)&ps_hi, g_ps_hi);
    cudaGetSymbolAddress((void**)&ps_lo, g_ps_lo);
    cudaGetSymbolAddress((void**)&qh2_hi, g_qh2_hi);
    cudaGetSymbolAddress((void**)&qh2_lo, g_qh2_lo);
    cudaGetSymbolAddress((void**)&w2s_hi, g_w2s_hi);
    cudaGetSymbolAddress((void**)&w2s_lo, g_w2s_lo);
    cudaGetSymbolAddress((void**)&aout_hi, g_aout_hi);
    cudaGetSymbolAddress((void**)&aout_lo, g_aout_lo);
    cudaGetSymbolAddress((void**)&wt_hi, g_wt_hi);
    cudaGetSymbolAddress((void**)&wt_lo, g_wt_lo);
    cudaGetSymbolAddress((void**)&wcat_hi, g_wcat_hi);
    cudaGetSymbolAddress((void**)&wcat_lo, g_wcat_lo);
    cudaGetSymbolAddress((void**)&qh,     g_qh);
    cudaGetSymbolAddress((void**)&kv,     g_kv);
    cudaGetSymbolAddress((void**)&hidden, g_hidden);
    cudaGetSymbolAddress((void**)&wtilde, g_wtilde);
    cudaGetSymbolAddress((void**)&wfold,  g_wfold);
    cudaGetSymbolAddress((void**)&bfold,  g_bfold);

    // fork
    detect_idx_kernel<<<1, 32>>>(lidx);
    cudaEventRecord(ev0, 0);
    cudaStreamWaitEvent(s1, ev0, 0);
    cudaStreamWaitEvent(s2, ev0, 0);

    // ---- s0 (critical path): W1T split, then pos split + W1 GEMM in 2 halves
    {
        splitT_kernel<<<(W1_SZ + 255) / 256, 256>>>(
            W1, wt_hi + W1_OFF, wt_lo + W1_OFF, DHIDDEN, DHIDDEN, DHIDDEN, 0);
        const size_t half_rows = ROWS_BIJ / 2;              // 32768
        const size_t half_elems = half_rows * DHIDDEN;      // 16.7M
        for (int hf = 0; hf < 2; hf++) {
            size_t eoff = (size_t)hf * half_elems;
            size_t n4 = half_elems / 4;
            split_kernel<<<(unsigned)((n4 + 255) / 256), 256>>>(
                pos + eoff, ps_hi + eoff, ps_lo + eoff, n4);
            TG_SLIM<<<dim3(DHIDDEN / 64, half_rows / 128), 256, SMEM_SLIM>>>(
                ps_hi + eoff, ps_lo + eoff, DHIDDEN, 0,
                wt_hi + W1_OFF, wt_lo + W1_OFF, DHIDDEN, 0,
                b1, hidden + eoff, nullptr, nullptr, DHIDDEN, 0, DHIDDEN,
                FL_F32 | FL_RELU);
        }
    }

    // ---- s1: q path + wtilde
    {
        size_t n4 = (size_t)ROWS_BI * DMODEL / 4;
        split_kernel<<<(unsigned)((n4 + 255) / 256), 256, 0, s1>>>(q, qs_hi, qs_lo, n4);
        splitT_kernel<<<(WQ_SZ + 255) / 256, 256, 0, s1>>>(
            Wq, wt_hi + WQ_OFF, wt_lo + WQ_OFF, DMODEL, DHIDDEN, DMODEL, 0);
        TG_BIG<<<dim3(4, 32, 1), 256, SMEM_BIG, s1>>>(
            qs_hi, qs_lo, DMODEL, 0,
            wt_hi + WQ_OFF, wt_lo + WQ_OFF, DMODEL, 0,
            nullptr, qh, qh2_hi, qh2_lo, DHIDDEN, 0, DMODEL, FL_F32 | FL_SPLIT);
        size_t w4 = (size_t)DHIDDEN * 2 * DHIDDEN / 4;
        split_kernel<<<(unsigned)((w4 + 255) / 256), 256, 0, s1>>>(W2, w2s_hi, w2s_lo, w4);
        TG_BIG<<<dim3(4, 32, 8), 256, SMEM_BIG, s1>>>(
            qh2_hi, qh2_lo, DHIDDEN, 64,
            w2s_hi, w2s_lo, 2 * DHIDDEN, 128,
            nullptr, wtilde, nullptr, nullptr, HH * DHIDDEN, 512, 64, FL_F32);
        cudaEventRecord(ev1, s1);
    }

    // ---- s2: k path + folded output weights
    {
        size_t n4 = (size_t)ROWS_BI * DMODEL / 4;
        split_kernel<<<(unsigned)((n4 + 255) / 256), 256, 0, s2>>>(k, ks_hi, ks_lo, n4);
        splitT_kernel<<<(WKV_SZ + 255) / 256, 256, 0, s2>>>(
            Wkv, wt_hi + WKV_OFF, wt_lo + WKV_OFF, DMODEL, 2 * DHIDDEN, DMODEL, 0);
        TG_BIG<<<dim3(8, 32, 1), 256, SMEM_BIG, s2>>>(
            ks_hi, ks_lo, DMODEL, 0,
            wt_hi + WKV_OFF, wt_lo + WKV_OFF, DMODEL, 0,
            nullptr, kv, nullptr, nullptr, 2 * DHIDDEN, 0, DMODEL, FL_F32);
        prep_fold_kernel<<<HH * DHIDDEN, 256, 0, s2>>>(W2, Wout, wfold);
        prep_bfold_kernel<<<1, 256, 0, s2>>>(b2, Wout, bfold);
        splitT_kernel<<<(DHIDDEN * DMODEL + 255) / 256, 256, 0, s2>>>(
            Wout, wcat_hi, wcat_lo, DHIDDEN, DMODEL, KCAT, 0);
        splitT_kernel<<<(HH * DHIDDEN * DMODEL + 255) / 256, 256, 0, s2>>>(
            wfold, wcat_hi, wcat_lo, HH * DHIDDEN, DMODEL, KCAT, DHIDDEN);
        cudaEventRecord(ev2, s2);
    }

    // join side branches into s0 before attention
    cudaStreamWaitEvent(0, ev1, 0);
    cudaStreamWaitEvent(0, ev2, 0);

    // ---- attention in 2 halves; out-GEMM half0 overlaps attn half1 on s1
    attn_fused_kernel<<<ROWS_BI / 2, 256, AT_SMEM>>>(
        qh, kv, hidden, wtilde, lidx, aout_hi, aout_lo, 0);
    cudaEventRecord(eva0, 0);
    attn_fused_kernel<<<ROWS_BI / 2, 256, AT_SMEM>>>(
        qh, kv, hidden, wtilde, lidx, aout_hi, aout_lo, ROWS_BI / 2);

    // s1: out half0 (rows 0..2047) after attn half0 (wcat ready via ev2->s0 order;
    //     wait ev2 on s1 explicitly too)
    cudaStreamWaitEvent(s1, eva0, 0);
    cudaStreamWaitEvent(s1, ev2, 0);
    TG_OUT<<<dim3(DMODEL / 64, (ROWS_BI / 2) / 64), 256, SMEM_OUT, s1>>>(
        aout_hi, aout_lo, KCAT, 0,
        wcat_hi, wcat_lo, KCAT, 0,
        bfold, out, nullptr, nullptr, DMODEL, 0, KCAT, FL_F32);
    cudaEventRecord(evo0, s1);

    // s0: out half1 (rows 2048..4095)
    {
        const size_t roff = (size_t)(ROWS_BI / 2);
        TG_OUT<<<dim3(DMODEL / 64, (ROWS_BI / 2) / 64), 256, SMEM_OUT>>>(
            aout_hi + roff * KCAT, aout_lo + roff * KCAT, KCAT, 0,
            wcat_hi, wcat_lo, KCAT, 0,
            bfold, out + roff * DMODEL, nullptr, nullptr, DMODEL, 0, KCAT, FL_F32);
    }

    // final join
    cudaStreamWaitEvent(0, evo0, 0);
}

// round 14
// speedup vs baseline: 1.0635x; 1.0635x over previous
#include <cuda_runtime.h>
#include <cuda_bf16.h>
#include <math.h>
#include <stdint.h>

// ---------------------------------------------------------------------------
// Problem constants
// ---------------------------------------------------------------------------
#define BB      2
#define II      2048
#define JJ      16
#define NKK     2048
#define DMODEL  256
#define DHIDDEN 512
#define HH      8
#define DK      64

#define ROWS_BI   (BB * II)            // 4096
#define ROWS_BIJ  (BB * II * JJ)       // 65536

#define KCAT (DHIDDEN + HH * DHIDDEN)  // 4608

// ---------------------------------------------------------------------------
// Scratch (device globals — no allocation allowed)
// ---------------------------------------------------------------------------
__device__ __nv_bfloat16 g_qs_hi[ROWS_BI * DMODEL];
__device__ __nv_bfloat16 g_qs_lo[ROWS_BI * DMODEL];
__device__ __nv_bfloat16 g_ks_hi[ROWS_BI * DMODEL];
__device__ __nv_bfloat16 g_ks_lo[ROWS_BI * DMODEL];
__device__ __nv_bfloat16 g_ps_hi[(size_t)ROWS_BIJ * DHIDDEN];   // 64 MB
__device__ __nv_bfloat16 g_ps_lo[(size_t)ROWS_BIJ * DHIDDEN];   // 64 MB

__device__ __nv_bfloat16 g_qh2_hi[ROWS_BI * DHIDDEN];
__device__ __nv_bfloat16 g_qh2_lo[ROWS_BI * DHIDDEN];
__device__ __nv_bfloat16 g_w2s_hi[DHIDDEN * 2 * DHIDDEN];
__device__ __nv_bfloat16 g_w2s_lo[DHIDDEN * 2 * DHIDDEN];

// combined attention output: [4096, 4608]  (akv | hbar)
__device__ __nv_bfloat16 g_aout_hi[(size_t)ROWS_BI * KCAT];   // 37.7 MB
__device__ __nv_bfloat16 g_aout_lo[(size_t)ROWS_BI * KCAT];   // 37.7 MB

// transposed split weights (q/kv/W1 paths)
#define WQ_OFF   0
#define WQ_SZ    (DHIDDEN * DMODEL)
#define WKV_OFF  (WQ_OFF + WQ_SZ)
#define WKV_SZ   (2 * DHIDDEN * DMODEL)
#define W1_OFF   (WKV_OFF + WKV_SZ)
#define W1_SZ    (DHIDDEN * DHIDDEN)
#define WT_TOTAL (W1_OFF + W1_SZ)

__device__ __nv_bfloat16 g_wt_hi[WT_TOTAL];
__device__ __nv_bfloat16 g_wt_lo[WT_TOTAL];

// concatenated output weight [256, 4608]: [0,512)=WoutT, [512,4608)=WfoldT
__device__ __nv_bfloat16 g_wcat_hi[DMODEL * KCAT];
__device__ __nv_bfloat16 g_wcat_lo[DMODEL * KCAT];

__device__ float g_qh[ROWS_BI * DHIDDEN];
__device__ float g_kv[ROWS_BI * 2 * DHIDDEN];
__device__ float g_hidden[(size_t)ROWS_BIJ * DHIDDEN];     // 128 MB fp32
__device__ float g_wtilde[(size_t)ROWS_BI * HH * DHIDDEN]; // 64 MB fp32
__device__ float g_wfold[HH * DHIDDEN * DMODEL];           // 4 MB fp32
__device__ float g_bfold[DMODEL];
__device__ int   g_idx_is64;

// ---------------------------------------------------------------------------
// local_idx dtype detection
// ---------------------------------------------------------------------------
__global__ void detect_idx_kernel(const void* idx_raw) {
    if (threadIdx.x == 0 && blockIdx.x == 0) {
        const long long* p = (const long long*)idx_raw;
        int is64 = 1;
        for (int s = 0; s < 64; s++) {
            long long v = p[s * 37];
            if (v < 0 || v >= NKK) { is64 = 0; break; }
        }
        g_idx_is64 = is64;
    }
}

// ---------------------------------------------------------------------------
// fp32 -> (bf16 hi, bf16 lo) split, vectorized by 4
// ---------------------------------------------------------------------------
__global__ void split_kernel(const float* __restrict__ x,
                             __nv_bfloat16* __restrict__ hi,
                             __nv_bfloat16* __restrict__ lo, size_t n4)
{
    size_t i = ((size_t)blockIdx.x * blockDim.x + threadIdx.x);
    if (i >= n4) return;
    float4 v = ((const float4*)x)[i];
    __nv_bfloat16 h0 = __float2bfloat16(v.x);
    __nv_bfloat16 h1 = __float2bfloat16(v.y);
    __nv_bfloat16 h2 = __float2bfloat16(v.z);
    __nv_bfloat16 h3 = __float2bfloat16(v.w);
    __nv_bfloat16 l0 = __float2bfloat16(v.x - __bfloat162float(h0));
    __nv_bfloat16 l1 = __float2bfloat16(v.y - __bfloat162float(h1));
    __nv_bfloat16 l2 = __float2bfloat16(v.z - __bfloat162float(h2));
    __nv_bfloat16 l3 = __float2bfloat16(v.w - __bfloat162float(h3));
    __nv_bfloat162* hp = (__nv_bfloat162*)(hi + i * 4);
    __nv_bfloat162* lp = (__nv_bfloat162*)(lo + i * 4);
    hp[0] = __nv_bfloat162(h0, h1); hp[1] = __nv_bfloat162(h2, h3);
    lp[0] = __nv_bfloat162(l0, l1); lp[1] = __nv_bfloat162(l2, l3);
}

// split + transpose weights: W[K,N] -> Wt_hi/lo[N, out_ld] at column out_off
__global__ void splitT_kernel(const float* __restrict__ W,
                              __nv_bfloat16* __restrict__ thi,
                              __nv_bfloat16* __restrict__ tlo,
                              int K, int N, int out_ld, int out_off)
{
    int idx = blockIdx.x * 256 + threadIdx.x;
    if (idx >= K * N) return;
    int k = idx / N, n = idx % N;
    float v = W[idx];
    __nv_bfloat16 h = __float2bfloat16(v);
    __nv_bfloat16 l = __float2bfloat16(v - __bfloat162float(h));
    thi[(size_t)n * out_ld + out_off + k] = h;
    tlo[(size_t)n * out_ld + out_off + k] = l;
}

// ---------------------------------------------------------------------------
// Wfold[(h*512+c), m] = sum_d W2[c, h*128+64+d] * Wout[h*64+d, m]
// bfold[m] = sum_{h,d} b2[h*128+64+d] * Wout[h*64+d, m]
// ---------------------------------------------------------------------------
__global__ void prep_fold_kernel(const float* __restrict__ W2,
                                 const float* __restrict__ Wout,
                                 float* __restrict__ Wfold)
{
    const int hc = blockIdx.x;
    const int h = hc >> 9, c = hc & 511;
    __shared__ float w2s[64];
    if (threadIdx.x < 64)
        w2s[threadIdx.x] = W2[c * 1024 + h * 128 + 64 + threadIdx.x];
    __syncthreads();
    const int m = threadIdx.x;
    float a = 0.0f;
    #pragma unroll 8
    for (int d = 0; d < 64; d++)
        a = fmaf(w2s[d], Wout[(h * 64 + d) * 256 + m], a);
    Wfold[(size_t)hc * 256 + m] = a;
}

__global__ void prep_bfold_kernel(const float* __restrict__ b2,
                                  const float* __restrict__ Wout,
                                  float* __restrict__ bfold)
{
    const int m = threadIdx.x;
    float a = 0.0f;
    for (int h = 0; h < 8; h++)
        for (int d = 0; d < 64; d++)
            a = fmaf(b2[h * 128 + 64 + d], Wout[(h * 64 + d) * 256 + m], a);
    bfold[m] = a;
}

// ---------------------------------------------------------------------------
// mma.sync helpers
// ---------------------------------------------------------------------------
__device__ __forceinline__ uint32_t smem_u32(const void* p) {
    uint32_t a;
    asm("{ .reg .u64 t; cvta.to.shared.u64 t, %1; cvt.u32.u64 %0, t; }"
        : "=r"(a) : "l"(p));
    return a;
}

#define SW128(o) ((o) ^ (((o) >> 3) & 0x70))

__device__ __forceinline__ void cp_async16(uint32_t saddr, const void* gaddr) {
    asm volatile("cp.async.cg.shared.global [%0], [%1], 16;"
                 :: "r"(saddr), "l"(gaddr));
}
__device__ __forceinline__ void ldsm_x4(uint32_t& a0, uint32_t& a1,
                                        uint32_t& a2, uint32_t& a3, uint32_t addr) {
    asm volatile("ldmatrix.sync.aligned.m8n8.x4.shared.b16 {%0,%1,%2,%3}, [%4];"
                 : "=r"(a0), "=r"(a1), "=r"(a2), "=r"(a3) : "r"(addr));
}
__device__ __forceinline__ void mma16816(float* c, const uint32_t* a,
                                         uint32_t b0, uint32_t b1) {
    asm volatile(
        "mma.sync.aligned.m16n8k16.row.col.f32.bf16.bf16.f32 "
        "{%0,%1,%2,%3}, {%4,%5,%6,%7}, {%8,%9}, {%0,%1,%2,%3};"
        : "+f"(c[0]), "+f"(c[1]), "+f"(c[2]), "+f"(c[3])
        : "r"(a[0]), "r"(a[1]), "r"(a[2]), "r"(a[3]), "r"(b0), "r"(b1));
}

// ---------------------------------------------------------------------------
// Tensor-core GEMM via mma.sync (split bf16, 3-term) — exact R9 configuration
// (2-stage, measured best). C[ROWS x NT tile] = A[M,K](lda) @ Wt[N,K](ldb)^T
// ---------------------------------------------------------------------------
#define FL_F32   1
#define FL_SPLIT 2
#define FL_RELU  4

template<int WGM, int WGN, int MI, int NI, int OCC>
__global__ __launch_bounds__(256, OCC) void tgemm_kernel(
    const __nv_bfloat16* __restrict__ Ahi, const __nv_bfloat16* __restrict__ Alo,
    int lda, size_t a_zs,
    const __nv_bfloat16* __restrict__ Bhi, const __nv_bfloat16* __restrict__ Blo,
    int ldb, size_t b_zs,
    const float* __restrict__ bias,
    float* __restrict__ Cf,
    __nv_bfloat16* __restrict__ Chi, __nv_bfloat16* __restrict__ Clo,
    int ldc, size_t c_zs,
    int K, int flags)
{
    static_assert(NI % 2 == 0, "NI must be even for x4 B loads");
    constexpr int ROWS    = WGM * MI * 16;
    constexpr int NT      = WGN * NI * 8;
    constexpr int A_BYTES = ROWS * 128;            // per hi / per lo
    constexpr int B_BYTES = NT * 128;
    constexpr int SB_HI   = 2 * A_BYTES;
    constexpr int SB_LO   = 2 * A_BYTES + B_BYTES;
    constexpr int STB     = 2 * A_BYTES + 2 * B_BYTES;   // stage bytes
    constexpr int BS      = NT + 4;                // epilogue buf stride

    extern __shared__ char smem_raw[];
    uint32_t base0 = smem_u32(smem_raw);
    uint32_t base  = (base0 + 1023) & ~1023u;
    char*    smem  = smem_raw + (base - base0);

    const int tid  = threadIdx.x;
    const int warp = tid >> 5, lane = tid & 31;
    const int wm = warp / WGN, wn = warp % WGN;
    const int rowA0 = blockIdx.y * ROWS;
    const int rowB0 = blockIdx.x * NT;
    const size_t z = blockIdx.z;

    const __nv_bfloat16* AhiZ = Ahi + z * a_zs;
    const __nv_bfloat16* AloZ = Alo + z * a_zs;
    const __nv_bfloat16* BhiZ = Bhi + z * b_zs;
    const __nv_bfloat16* BloZ = Blo + z * b_zs;

    float acc[MI][NI][4];
    #pragma unroll
    for (int mi = 0; mi < MI; mi++)
        #pragma unroll
        for (int ni = 0; ni < NI; ni++)
            #pragma unroll
            for (int r = 0; r < 4; r++) acc[mi][ni][r] = 0.0f;

    const int nchunks = K >> 6;

    auto load_chunk = [&](int chunk, int stage) {
        const int k0 = chunk << 6;
        uint32_t st = base + stage * STB;
        #pragma unroll
        for (int l = 0; l < ROWS * 8 / 256; l++) {
            int id = tid + (l << 8);
            int r = id >> 3, c = id & 7;
            uint32_t so = SW128((uint32_t)(r * 128 + c * 16));
            size_t ga = (size_t)(rowA0 + r) * lda + k0 + (c << 3);
            cp_async16(st + so, AhiZ + ga);
            cp_async16(st + A_BYTES + so, AloZ + ga);
        }
        #pragma unroll
        for (int l = 0; l < NT * 8 / 256; l++) {
            int id = tid + (l << 8);
            int r = id >> 3, c = id & 7;
            uint32_t so = SW128((uint32_t)(r * 128 + c * 16));
            size_t gb = (size_t)(rowB0 + r) * ldb + k0 + (c << 3);
            cp_async16(st + SB_HI + so, BhiZ + gb);
            cp_async16(st + SB_LO + so, BloZ + gb);
        }
        asm volatile("cp.async.commit_group;");
    };

    const int a_row_l = wm * (MI * 16) + (lane & 15);
    const int a_cb_l  = (lane >> 4) << 4;
    const int b_row_l = wn * (NI * 8) + (lane & 7) + ((lane >> 4) << 3);
    const int b_cb_l  = ((lane >> 3) & 1) << 4;

    load_chunk(0, 0);

    for (int i = 0; i < nchunks; i++) {
        const int s = i & 1;
        if (i + 1 < nchunks) {
            load_chunk(i + 1, 1 - s);
            asm volatile("cp.async.wait_group 1;");
        } else {
            asm volatile("cp.async.wait_group 0;");
        }
        __syncthreads();

        const uint32_t st = base + s * STB;
        #pragma unroll
        for (int ks = 0; ks < 4; ks++) {
            const int kb = ks << 5;
            uint32_t ah[MI][4], al[MI][4], bh[NI][2], bl[NI][2];
            #pragma unroll
            for (int mi = 0; mi < MI; mi++) {
                uint32_t so = SW128((uint32_t)((a_row_l + mi * 16) * 128 + kb + a_cb_l));
                ldsm_x4(ah[mi][0], ah[mi][1], ah[mi][2], ah[mi][3], st + so);
                ldsm_x4(al[mi][0], al[mi][1], al[mi][2], al[mi][3], st + A_BYTES + so);
            }
            #pragma unroll
            for (int p = 0; p < NI / 2; p++) {
                uint32_t off = SW128((uint32_t)((b_row_l + p * 16) * 128 + kb + b_cb_l));
                ldsm_x4(bh[2 * p][0], bh[2 * p][1], bh[2 * p + 1][0], bh[2 * p + 1][1],
                        st + SB_HI + off);
                ldsm_x4(bl[2 * p][0], bl[2 * p][1], bl[2 * p + 1][0], bl[2 * p + 1][1],
                        st + SB_LO + off);
            }
            #pragma unroll
            for (int ni = 0; ni < NI; ni++)
                #pragma unroll
                for (int mi = 0; mi < MI; mi++) {
                    mma16816(acc[mi][ni], ah[mi], bh[ni][0], bh[ni][1]);
                    mma16816(acc[mi][ni], ah[mi], bl[ni][0], bl[ni][1]);
                    mma16816(acc[mi][ni], al[mi], bh[ni][0], bh[ni][1]);
                }
        }
        __syncthreads();
    }

    // ---- epilogue: regs -> SMEM bounce (stride BS f32) -> global
    float* buf = (float*)smem;
    {
        const int r0 = wm * (MI * 16) + (lane >> 2);
        const int c0 = wn * (NI * 8) + ((lane & 3) << 1);
        #pragma unroll
        for (int mi = 0; mi < MI; mi++)
            #pragma unroll
            for (int ni = 0; ni < NI; ni++) {
                int rr = r0 + mi * 16;
                int cc = c0 + ni * 8;
                buf[rr * BS + cc]           = acc[mi][ni][0];
                buf[rr * BS + cc + 1]       = acc[mi][ni][1];
                buf[(rr + 8) * BS + cc]     = acc[mi][ni][2];
                buf[(rr + 8) * BS + cc + 1] = acc[mi][ni][3];
            }
    }
    __syncthreads();

    {
        constexpr int TPR = 256 / ROWS;         // threads per row
        constexpr int CPT = NT / TPR;           // cols per thread
        const int rloc = tid / TPR;
        const int colb = (tid % TPR) * CPT;
        const size_t grow = (size_t)(rowA0 + rloc);
        float vals[CPT];
        #pragma unroll
        for (int c = 0; c < CPT; c++) {
            float v = buf[rloc * BS + colb + c];
            if (bias) v += bias[rowB0 + colb + c];
            if (flags & FL_RELU) v = fmaxf(v, 0.0f);
            vals[c] = v;
        }
        if (flags & FL_F32) {
            float* crow = Cf + z * c_zs + grow * ldc + rowB0 + colb;
            #pragma unroll
            for (int c = 0; c < CPT; c += 4) {
                float4 o = {vals[c], vals[c + 1], vals[c + 2], vals[c + 3]};
                *(float4*)(crow + c) = o;
            }
        }
        if (flags & FL_SPLIT) {
            __nv_bfloat16* hrow = Chi + z * c_zs + grow * ldc + rowB0 + colb;
            __nv_bfloat16* lrow = Clo + z * c_zs + grow * ldc + rowB0 + colb;
            #pragma unroll
            for (int c = 0; c < CPT; c += 8) {
                __nv_bfloat16 hv[8], lv[8];
                #pragma unroll
                for (int u = 0; u < 8; u++) {
                    float v = vals[c + u];
                    hv[u] = __float2bfloat16(v);
                    lv[u] = __float2bfloat16(v - __bfloat162float(hv[u]));
                }
                *(uint4*)(hrow + c) = *(uint4*)hv;
                *(uint4*)(lrow + c) = *(uint4*)lv;
            }
        }
    }
}

// variants: BIG 128x128 (occ1), SLIM 128x64 (occ2) — R9 exact
#define TG_BIG  tgemm_kernel<2, 4, 4, 4, 1>
#define TG_SLIM tgemm_kernel<4, 2, 2, 4, 2>
#define SMEM_BIG  (1024 + 2 * (2 * 128 * 128 + 2 * 128 * 128))   // 132096
#define SMEM_SLIM (1024 + 2 * (2 * 128 * 128 + 2 * 64 * 128))    // 99328

// ---------------------------------------------------------------------------
// Fused attention v2 (R12): register-reuse logits + loop-swapped hbar.
// ---------------------------------------------------------------------------
#define HS 516              // hid row stride (floats)
#define WS 516              // wt row stride
#define QS 68               // qvp row stride
#define PS_ 132             // part cb stride
#define SM_QV   0
#define SM_WT   (8 * QS)                    // 544
#define SM_HID  (SM_WT + 8 * WS)            // 4672
#define SM_VV   (SM_HID + 16 * HS)          // 12928
#define SM_PART (SM_VV + 16 * 512)          // 21120
#define AT_FLOATS (SM_PART + 16 * PS_ + 16)
#define AT_SMEM (AT_FLOATS * 4)

__global__ __launch_bounds__(256) void attn_fused_kernel(
    const float* __restrict__ qh, const float* __restrict__ kvb,
    const float* __restrict__ hidden, const float* __restrict__ wtilde,
    const void* __restrict__ idx_raw,
    __nv_bfloat16* __restrict__ aout_hi, __nv_bfloat16* __restrict__ aout_lo)
{
    extern __shared__ float sm[];
    float* qvp  = sm + SM_QV;
    float* wt   = sm + SM_WT;
    float* hid  = sm + SM_HID;
    float* vv   = sm + SM_VV;
    float* part = sm + SM_PART;
    __shared__ int   sidx[JJ];
    __shared__ float lg[JJ][HH];
    __shared__ __align__(16) float aw[JJ][HH];

    const int row = blockIdx.x;
    const int b   = row >> 11;
    const int t   = threadIdx.x;

    if (t < JJ) {
        long long n;
        if (g_idx_is64) n = ((const long long*)idx_raw)[(size_t)row * JJ + t];
        else            n = ((const int*)idx_raw)[(size_t)row * JJ + t];
        sidx[t] = b * NKK + (int)n;
    }
    #pragma unroll
    for (int rep = 0; rep < 2; rep++) {
        int o = t + (rep << 8);
        qvp[(o >> 6) * QS + (o & 63)] = qh[(size_t)row * 512 + o];
    }
    {
        const float4* wsrc = (const float4*)(wtilde + (size_t)row * 4096);
        #pragma unroll
        for (int l = 0; l < 4; l++) {
            int i4 = t + (l << 8);
            int h = i4 >> 7, c = (i4 & 127) << 2;
            *(float4*)(wt + h * WS + c) = wsrc[i4];
        }
        const float4* hsrc = (const float4*)(hidden + (size_t)row * JJ * 512);
        #pragma unroll
        for (int l = 0; l < 8; l++) {
            int i4 = t + (l << 8);
            int j = i4 >> 7, c = (i4 & 127) << 2;
            *(float4*)(hid + j * HS + c) = hsrc[i4];
        }
    }
    __syncthreads();
    #pragma unroll
    for (int j = 0; j < JJ; j++) {
        const float2* vp = (const float2*)(kvb + (size_t)sidx[j] * 1024 + 512);
        ((float2*)(vv + j * 512))[t] = vp[t];
    }

    // ---- logits partials: thread = (cb, j); 32 hid floats cached in regs
    {
        const int cb = t >> 4;          // 0..15
        const int j  = t & 15;
        float h32[32];
        const float* hrow = hid + j * HS + cb * 32;
        #pragma unroll
        for (int i = 0; i < 32; i += 4) {
            float4 v = *(const float4*)(hrow + i);
            h32[i] = v.x; h32[i + 1] = v.y; h32[i + 2] = v.z; h32[i + 3] = v.w;
        }
        const int stag = (cb & 1) << 4;
        #pragma unroll
        for (int h = 0; h < 8; h++) {
            const float* wrow = wt + h * WS + cb * 32;
            float p = 0.0f;
            #pragma unroll
            for (int ii = 0; ii < 32; ii++) {
                int i = (ii + stag) & 31;
                p = fmaf(h32[i], wrow[i], p);
            }
            part[cb * PS_ + j * 8 + h] = p;
        }
    }
    __syncthreads();

    // ---- reduce partials + q.k term
    if (t < JJ * HH) {
        const int j = t >> 3, h = t & 7;
        float s = 0.0f;
        #pragma unroll
        for (int cb = 0; cb < 16; cb++) s += part[cb * PS_ + j * 8 + h];
        const float* kp = kvb + (size_t)sidx[j] * 1024 + h * 64;
        const float* qp = qvp + h * QS;
        #pragma unroll
        for (int d = 0; d < 64; d += 4) {
            float4 k4 = *(const float4*)(kp + d);
            s = fmaf(qp[d + 0], k4.x, s);
            s = fmaf(qp[d + 1], k4.y, s);
            s = fmaf(qp[d + 2], k4.z, s);
            s = fmaf(qp[d + 3], k4.w, s);
        }
        lg[j][h] = s * 0.125f;
    }
    __syncthreads();

    if (t < HH) {
        float m = -1e30f;
        #pragma unroll
        for (int j = 0; j < JJ; j++) m = fmaxf(m, lg[j][t]);
        float ssum = 0.0f;
        #pragma unroll
        for (int j = 0; j < JJ; j++) {
            float e = expf(lg[j][t] - m);
            aw[j][t] = e;
            ssum += e;
        }
        float inv = 1.0f / ssum;
        #pragma unroll
        for (int j = 0; j < JJ; j++) aw[j][t] *= inv;
    }
    __syncthreads();

    // ---- akv
    #pragma unroll
    for (int rep = 0; rep < 2; rep++) {
        int o = t + (rep << 8);
        int h = o >> 6, d = o & 63;
        float a = 0.0f;
        #pragma unroll
        for (int j = 0; j < JJ; j++)
            a = fmaf(aw[j][h], vv[j * 512 + h * 64 + d], a);
        __nv_bfloat16 hv = __float2bfloat16(a);
        __nv_bfloat16 lv = __float2bfloat16(a - __bfloat162float(hv));
        aout_hi[(size_t)row * KCAT + o] = hv;
        aout_lo[(size_t)row * KCAT + o] = lv;
    }

    // ---- hbar loop-swapped
    {
        const int c0 = t << 1;
        float a2[8][2];
        #pragma unroll
        for (int h = 0; h < 8; h++) { a2[h][0] = 0.0f; a2[h][1] = 0.0f; }
        #pragma unroll
        for (int j = 0; j < JJ; j++) {
            float2 v = *(const float2*)(hid + j * HS + c0);
            float4 w0 = *(const float4*)(&aw[j][0]);
            float4 w1 = *(const float4*)(&aw[j][4]);
            a2[0][0] = fmaf(w0.x, v.x, a2[0][0]); a2[0][1] = fmaf(w0.x, v.y, a2[0][1]);
            a2[1][0] = fmaf(w0.y, v.x, a2[1][0]); a2[1][1] = fmaf(w0.y, v.y, a2[1][1]);
            a2[2][0] = fmaf(w0.z, v.x, a2[2][0]); a2[2][1] = fmaf(w0.z, v.y, a2[2][1]);
            a2[3][0] = fmaf(w0.w, v.x, a2[3][0]); a2[3][1] = fmaf(w0.w, v.y, a2[3][1]);
            a2[4][0] = fmaf(w1.x, v.x, a2[4][0]); a2[4][1] = fmaf(w1.x, v.y, a2[4][1]);
            a2[5][0] = fmaf(w1.y, v.x, a2[5][0]); a2[5][1] = fmaf(w1.y, v.y, a2[5][1]);
            a2[6][0] = fmaf(w1.z, v.x, a2[6][0]); a2[6][1] = fmaf(w1.z, v.y, a2[6][1]);
            a2[7][0] = fmaf(w1.w, v.x, a2[7][0]); a2[7][1] = fmaf(w1.w, v.y, a2[7][1]);
        }
        #pragma unroll
        for (int h = 0; h < 8; h++) {
            __nv_bfloat16 h0 = __float2bfloat16(a2[h][0]);
            __nv_bfloat16 h1 = __float2bfloat16(a2[h][1]);
            __nv_bfloat16 l0 = __float2bfloat16(a2[h][0] - __bfloat162float(h0));
            __nv_bfloat16 l1 = __float2bfloat16(a2[h][1] - __bfloat162float(h1));
            size_t ob = (size_t)row * KCAT + 512 + h * 512 + c0;
            *(__nv_bfloat162*)(aout_hi + ob) = __nv_bfloat162(h0, h1);
            *(__nv_bfloat162*)(aout_lo + ob) = __nv_bfloat162(l0, l1);
        }
    }
}

// ---------------------------------------------------------------------------
// Launch: exact R12 schedule; out-GEMM on SLIM tile (only change vs R12)
// inputs: 0:q 1:k 2:pos 3:local_idx 4:Wq 5:Wkv 6:W1 7:b1 8:W2 9:b2 10:Wout
// ---------------------------------------------------------------------------
extern "C" void kernel_launch(void* const* d_in, const int* in_sizes, int n_in,
                              void* d_out, int out_size)
{
    const float* q    = (const float*)d_in[0];
    const float* k    = (const float*)d_in[1];
    const float* pos  = (const float*)d_in[2];
    const void*  lidx = d_in[3];
    const float* Wq   = (const float*)d_in[4];
    const float* Wkv  = (const float*)d_in[5];
    const float* W1   = (const float*)d_in[6];
    const float* b1   = (const float*)d_in[7];
    const float* W2   = (const float*)d_in[8];
    const float* b2   = (const float*)d_in[9];
    const float* Wout = (const float*)d_in[10];
    float* out = (float*)d_out;

    static cudaStream_t s1 = nullptr, s2 = nullptr;
    static cudaEvent_t ev0, ev1, ev2;
    static int init_done = 0;
    if (!init_done) {
        cudaStreamCreateWithFlags(&s1, cudaStreamNonBlocking);
        cudaStreamCreateWithFlags(&s2, cudaStreamNonBlocking);
        cudaEventCreateWithFlags(&ev0, cudaEventDisableTiming);
        cudaEventCreateWithFlags(&ev1, cudaEventDisableTiming);
        cudaEventCreateWithFlags(&ev2, cudaEventDisableTiming);
        cudaFuncSetAttribute(TG_BIG,
                             cudaFuncAttributeMaxDynamicSharedMemorySize, SMEM_BIG);
        cudaFuncSetAttribute(TG_SLIM,
                             cudaFuncAttributeMaxDynamicSharedMemorySize, SMEM_SLIM);
        cudaFuncSetAttribute(attn_fused_kernel,
                             cudaFuncAttributeMaxDynamicSharedMemorySize, AT_SMEM);
        init_done = 1;
    }

    __nv_bfloat16 *qs_hi, *qs_lo, *ks_hi, *ks_lo, *ps_hi, *ps_lo;
    __nv_bfloat16 *qh2_hi, *qh2_lo, *w2s_hi, *w2s_lo;
    __nv_bfloat16 *aout_hi, *aout_lo, *wt_hi, *wt_lo, *wcat_hi, *wcat_lo;
    float *qh, *kv, *hidden, *wtilde, *wfold, *bfold;
    cudaGetSymbolAddress((void**)&qs_hi, g_qs_hi);
    cudaGetSymbolAddress((void**)&qs_lo, g_qs_lo);
    cudaGetSymbolAddress((void**)&ks_hi, g_ks_hi);
    cudaGetSymbolAddress((void**)&ks_lo, g_ks_lo);
    cudaGetSymbolAddress((void**)&ps_hi, g_ps_hi);
    cudaGetSymbolAddress((void**)&ps_lo, g_ps_lo);
    cudaGetSymbolAddress((void**)&qh2_hi, g_qh2_hi);
    cudaGetSymbolAddress((void**)&qh2_lo, g_qh2_lo);
    cudaGetSymbolAddress((void**)&w2s_hi, g_w2s_hi);
    cudaGetSymbolAddress((void**)&w2s_lo, g_w2s_lo);
    cudaGetSymbolAddress((void**)&aout_hi, g_aout_hi);
    cudaGetSymbolAddress((void**)&aout_lo, g_aout_lo);
    cudaGetSymbolAddress((void**)&wt_hi, g_wt_hi);
    cudaGetSymbolAddress((void**)&wt_lo, g_wt_lo);
    cudaGetSymbolAddress((void**)&wcat_hi, g_wcat_hi);
    cudaGetSymbolAddress((void**)&wcat_lo, g_wcat_lo);
    cudaGetSymbolAddress((void**)&qh,     g_qh);
    cudaGetSymbolAddress((void**)&kv,     g_kv);
    cudaGetSymbolAddress((void**)&hidden, g_hidden);
    cudaGetSymbolAddress((void**)&wtilde, g_wtilde);
    cudaGetSymbolAddress((void**)&wfold,  g_wfold);
    cudaGetSymbolAddress((void**)&bfold,  g_bfold);

    // fork
    detect_idx_kernel<<<1, 32>>>(lidx);
    cudaEventRecord(ev0, 0);
    cudaStreamWaitEvent(s1, ev0, 0);
    cudaStreamWaitEvent(s2, ev0, 0);

    // ---- s0 (critical path): W1T split, then pos split + W1 GEMM in 2 halves
    {
        splitT_kernel<<<(W1_SZ + 255) / 256, 256>>>(
            W1, wt_hi + W1_OFF, wt_lo + W1_OFF, DHIDDEN, DHIDDEN, DHIDDEN, 0);
        const size_t half_rows = ROWS_BIJ / 2;              // 32768
        const size_t half_elems = half_rows * DHIDDEN;      // 16.7M
        for (int hf = 0; hf < 2; hf++) {
            size_t eoff = (size_t)hf * half_elems;
            size_t n4 = half_elems / 4;
            split_kernel<<<(unsigned)((n4 + 255) / 256), 256>>>(
                pos + eoff, ps_hi + eoff, ps_lo + eoff, n4);
            TG_SLIM<<<dim3(DHIDDEN / 64, half_rows / 128), 256, SMEM_SLIM>>>(
                ps_hi + eoff, ps_lo + eoff, DHIDDEN, 0,
                wt_hi + W1_OFF, wt_lo + W1_OFF, DHIDDEN, 0,
                b1, hidden + eoff, nullptr, nullptr, DHIDDEN, 0, DHIDDEN,
                FL_F32 | FL_RELU);
        }
    }

    // ---- s1: q path + wtilde
    {
        size_t n4 = (size_t)ROWS_BI * DMODEL / 4;
        split_kernel<<<(unsigned)((n4 + 255) / 256), 256, 0, s1>>>(q, qs_hi, qs_lo, n4);
        splitT_kernel<<<(WQ_SZ + 255) / 256, 256, 0, s1>>>(
            Wq, wt_hi + WQ_OFF, wt_lo + WQ_OFF, DMODEL, DHIDDEN, DMODEL, 0);
        TG_BIG<<<dim3(4, 32, 1), 256, SMEM_BIG, s1>>>(
            qs_hi, qs_lo, DMODEL, 0,
            wt_hi + WQ_OFF, wt_lo + WQ_OFF, DMODEL, 0,
            nullptr, qh, qh2_hi, qh2_lo, DHIDDEN, 0, DMODEL, FL_F32 | FL_SPLIT);
        size_t w4 = (size_t)DHIDDEN * 2 * DHIDDEN / 4;
        split_kernel<<<(unsigned)((w4 + 255) / 256), 256, 0, s1>>>(W2, w2s_hi, w2s_lo, w4);
        TG_BIG<<<dim3(4, 32, 8), 256, SMEM_BIG, s1>>>(
            qh2_hi, qh2_lo, DHIDDEN, 64,
            w2s_hi, w2s_lo, 2 * DHIDDEN, 128,
            nullptr, wtilde, nullptr, nullptr, HH * DHIDDEN, 512, 64, FL_F32);
        cudaEventRecord(ev1, s1);
    }

    // ---- s2: k path + folded output weights
    {
        size_t n4 = (size_t)ROWS_BI * DMODEL / 4;
        split_kernel<<<(unsigned)((n4 + 255) / 256), 256, 0, s2>>>(k, ks_hi, ks_lo, n4);
        splitT_kernel<<<(WKV_SZ + 255) / 256, 256, 0, s2>>>(
            Wkv, wt_hi + WKV_OFF, wt_lo + WKV_OFF, DMODEL, 2 * DHIDDEN, DMODEL, 0);
        TG_BIG<<<dim3(8, 32, 1), 256, SMEM_BIG, s2>>>(
            ks_hi, ks_lo, DMODEL, 0,
            wt_hi + WKV_OFF, wt_lo + WKV_OFF, DMODEL, 0,
            nullptr, kv, nullptr, nullptr, 2 * DHIDDEN, 0, DMODEL, FL_F32);
        prep_fold_kernel<<<HH * DHIDDEN, 256, 0, s2>>>(W2, Wout, wfold);
        prep_bfold_kernel<<<1, 256, 0, s2>>>(b2, Wout, bfold);
        splitT_kernel<<<(DHIDDEN * DMODEL + 255) / 256, 256, 0, s2>>>(
            Wout, wcat_hi, wcat_lo, DHIDDEN, DMODEL, KCAT, 0);
        splitT_kernel<<<(HH * DHIDDEN * DMODEL + 255) / 256, 256, 0, s2>>>(
            wfold, wcat_hi, wcat_lo, HH * DHIDDEN, DMODEL, KCAT, DHIDDEN);
        cudaEventRecord(ev2, s2);
    }

    // join
    cudaStreamWaitEvent(0, ev1, 0);
    cudaStreamWaitEvent(0, ev2, 0);

    // fused attention -> combined [akv | hbar]
    attn_fused_kernel<<<ROWS_BI, 256, AT_SMEM>>>(
        qh, kv, hidden, wtilde, lidx, aout_hi, aout_lo);

    // out = aout @ [Wout; Wfold]^T + bfold : M=4096, N=256, K=4608
    // SLIM 128x64 tile -> grid (4, 32) = 128 CTAs (swapped from 64x64 OUT)
    TG_SLIM<<<dim3(DMODEL / 64, ROWS_BI / 128), 256, SMEM_SLIM>>>(
        aout_hi, aout_lo, KCAT, 0,
        wcat_hi, wcat_lo, KCAT, 0,
        bfold, out, nullptr, nullptr, DMODEL, 0, KCAT, FL_F32);
}

// round 15
// speedup vs baseline: 1.1134x; 1.0469x over previous
#include <cuda_runtime.h>
#include <cuda_bf16.h>
#include <math.h>
#include <stdint.h>

// ---------------------------------------------------------------------------
// Problem constants
// ---------------------------------------------------------------------------
#define BB      2
#define II      2048
#define JJ      16
#define NKK     2048
#define DMODEL  256
#define DHIDDEN 512
#define HH      8
#define DK      64

#define ROWS_BI   (BB * II)            // 4096
#define ROWS_BIJ  (BB * II * JJ)       // 65536

#define KCAT (DHIDDEN + HH * DHIDDEN)  // 4608

// ---------------------------------------------------------------------------
// Scratch (device globals — no allocation allowed)
// ---------------------------------------------------------------------------
__device__ __nv_bfloat16 g_qs_hi[ROWS_BI * DMODEL];
__device__ __nv_bfloat16 g_qs_lo[ROWS_BI * DMODEL];
__device__ __nv_bfloat16 g_ks_hi[ROWS_BI * DMODEL];
__device__ __nv_bfloat16 g_ks_lo[ROWS_BI * DMODEL];
__device__ __nv_bfloat16 g_ps_hi[(size_t)ROWS_BIJ * DHIDDEN];   // 64 MB
__device__ __nv_bfloat16 g_ps_lo[(size_t)ROWS_BIJ * DHIDDEN];   // 64 MB

__device__ __nv_bfloat16 g_qh2_hi[ROWS_BI * DHIDDEN];
__device__ __nv_bfloat16 g_qh2_lo[ROWS_BI * DHIDDEN];
__device__ __nv_bfloat16 g_w2s_hi[DHIDDEN * 2 * DHIDDEN];
__device__ __nv_bfloat16 g_w2s_lo[DHIDDEN * 2 * DHIDDEN];

// combined attention output: [4096, 4608]  (akv | hbar)
__device__ __nv_bfloat16 g_aout_hi[(size_t)ROWS_BI * KCAT];   // 37.7 MB
__device__ __nv_bfloat16 g_aout_lo[(size_t)ROWS_BI * KCAT];   // 37.7 MB

// transposed split weights (q/kv/W1 paths)
#define WQ_OFF   0
#define WQ_SZ    (DHIDDEN * DMODEL)
#define WKV_OFF  (WQ_OFF + WQ_SZ)
#define WKV_SZ   (2 * DHIDDEN * DMODEL)
#define W1_OFF   (WKV_OFF + WKV_SZ)
#define W1_SZ    (DHIDDEN * DHIDDEN)
#define WT_TOTAL (W1_OFF + W1_SZ)

__device__ __nv_bfloat16 g_wt_hi[WT_TOTAL];
__device__ __nv_bfloat16 g_wt_lo[WT_TOTAL];

// concatenated output weight [256, 4608]: [0,512)=WoutT, [512,4608)=WfoldT
__device__ __nv_bfloat16 g_wcat_hi[DMODEL * KCAT];
__device__ __nv_bfloat16 g_wcat_lo[DMODEL * KCAT];

__device__ float g_qh[ROWS_BI * DHIDDEN];
__device__ float g_kv[ROWS_BI * 2 * DHIDDEN];
__device__ float g_hidden[(size_t)ROWS_BIJ * DHIDDEN];     // 128 MB fp32
__device__ float g_wtilde[(size_t)ROWS_BI * HH * DHIDDEN]; // 64 MB fp32
__device__ float g_wfold[HH * DHIDDEN * DMODEL];           // 4 MB fp32
__device__ float g_bfold[DMODEL];
__device__ int   g_idx_is64;

// ---------------------------------------------------------------------------
// local_idx dtype detection
// ---------------------------------------------------------------------------
__global__ void detect_idx_kernel(const void* idx_raw) {
    if (threadIdx.x == 0 && blockIdx.x == 0) {
        const long long* p = (const long long*)idx_raw;
        int is64 = 1;
        for (int s = 0; s < 64; s++) {
            long long v = p[s * 37];
            if (v < 0 || v >= NKK) { is64 = 0; break; }
        }
        g_idx_is64 = is64;
    }
}

// ---------------------------------------------------------------------------
// fp32 -> (bf16 hi, bf16 lo) split, vectorized by 4
// ---------------------------------------------------------------------------
__global__ void split_kernel(const float* __restrict__ x,
                             __nv_bfloat16* __restrict__ hi,
                             __nv_bfloat16* __restrict__ lo, size_t n4)
{
    size_t i = ((size_t)blockIdx.x * blockDim.x + threadIdx.x);
    if (i >= n4) return;
    float4 v = ((const float4*)x)[i];
    __nv_bfloat16 h0 = __float2bfloat16(v.x);
    __nv_bfloat16 h1 = __float2bfloat16(v.y);
    __nv_bfloat16 h2 = __float2bfloat16(v.z);
    __nv_bfloat16 h3 = __float2bfloat16(v.w);
    __nv_bfloat16 l0 = __float2bfloat16(v.x - __bfloat162float(h0));
    __nv_bfloat16 l1 = __float2bfloat16(v.y - __bfloat162float(h1));
    __nv_bfloat16 l2 = __float2bfloat16(v.z - __bfloat162float(h2));
    __nv_bfloat16 l3 = __float2bfloat16(v.w - __bfloat162float(h3));
    __nv_bfloat162* hp = (__nv_bfloat162*)(hi + i * 4);
    __nv_bfloat162* lp = (__nv_bfloat162*)(lo + i * 4);
    hp[0] = __nv_bfloat162(h0, h1); hp[1] = __nv_bfloat162(h2, h3);
    lp[0] = __nv_bfloat162(l0, l1); lp[1] = __nv_bfloat162(l2, l3);
}

// split + transpose weights: W[K,N] -> Wt_hi/lo[N, out_ld] at column out_off
__global__ void splitT_kernel(const float* __restrict__ W,
                              __nv_bfloat16* __restrict__ thi,
                              __nv_bfloat16* __restrict__ tlo,
                              int K, int N, int out_ld, int out_off)
{
    int idx = blockIdx.x * 256 + threadIdx.x;
    if (idx >= K * N) return;
    int k = idx / N, n = idx % N;
    float v = W[idx];
    __nv_bfloat16 h = __float2bfloat16(v);
    __nv_bfloat16 l = __float2bfloat16(v - __bfloat162float(h));
    thi[(size_t)n * out_ld + out_off + k] = h;
    tlo[(size_t)n * out_ld + out_off + k] = l;
}

// ---------------------------------------------------------------------------
// Wfold[(h*512+c), m] = sum_d W2[c, h*128+64+d] * Wout[h*64+d, m]
// bfold[m] = sum_{h,d} b2[h*128+64+d] * Wout[h*64+d, m]
// ---------------------------------------------------------------------------
__global__ void prep_fold_kernel(const float* __restrict__ W2,
                                 const float* __restrict__ Wout,
                                 float* __restrict__ Wfold)
{
    const int hc = blockIdx.x;
    const int h = hc >> 9, c = hc & 511;
    __shared__ float w2s[64];
    if (threadIdx.x < 64)
        w2s[threadIdx.x] = W2[c * 1024 + h * 128 + 64 + threadIdx.x];
    __syncthreads();
    const int m = threadIdx.x;
    float a = 0.0f;
    #pragma unroll 8
    for (int d = 0; d < 64; d++)
        a = fmaf(w2s[d], Wout[(h * 64 + d) * 256 + m], a);
    Wfold[(size_t)hc * 256 + m] = a;
}

__global__ void prep_bfold_kernel(const float* __restrict__ b2,
                                  const float* __restrict__ Wout,
                                  float* __restrict__ bfold)
{
    const int m = threadIdx.x;
    float a = 0.0f;
    for (int h = 0; h < 8; h++)
        for (int d = 0; d < 64; d++)
            a = fmaf(b2[h * 128 + 64 + d], Wout[(h * 64 + d) * 256 + m], a);
    bfold[m] = a;
}

// ---------------------------------------------------------------------------
// mma.sync helpers
// ---------------------------------------------------------------------------
__device__ __forceinline__ uint32_t smem_u32(const void* p) {
    uint32_t a;
    asm("{ .reg .u64 t; cvta.to.shared.u64 t, %1; cvt.u32.u64 %0, t; }"
        : "=r"(a) : "l"(p));
    return a;
}

#define SW128(o) ((o) ^ (((o) >> 3) & 0x70))

__device__ __forceinline__ void cp_async16(uint32_t saddr, const void* gaddr) {
    asm volatile("cp.async.cg.shared.global [%0], [%1], 16;"
                 :: "r"(saddr), "l"(gaddr));
}
__device__ __forceinline__ void ldsm_x4(uint32_t& a0, uint32_t& a1,
                                        uint32_t& a2, uint32_t& a3, uint32_t addr) {
    asm volatile("ldmatrix.sync.aligned.m8n8.x4.shared.b16 {%0,%1,%2,%3}, [%4];"
                 : "=r"(a0), "=r"(a1), "=r"(a2), "=r"(a3) : "r"(addr));
}
__device__ __forceinline__ void mma16816(float* c, const uint32_t* a,
                                         uint32_t b0, uint32_t b1) {
    asm volatile(
        "mma.sync.aligned.m16n8k16.row.col.f32.bf16.bf16.f32 "
        "{%0,%1,%2,%3}, {%4,%5,%6,%7}, {%8,%9}, {%0,%1,%2,%3};"
        : "+f"(c[0]), "+f"(c[1]), "+f"(c[2]), "+f"(c[3])
        : "r"(a[0]), "r"(a[1]), "r"(a[2]), "r"(a[3]), "r"(b0), "r"(b1));
}

// ---------------------------------------------------------------------------
// Tensor-core GEMM via mma.sync (split bf16, 3-term) — R9 configuration
// ---------------------------------------------------------------------------
#define FL_F32   1
#define FL_SPLIT 2
#define FL_RELU  4

template<int WGM, int WGN, int MI, int NI, int OCC>
__global__ __launch_bounds__(256, OCC) void tgemm_kernel(
    const __nv_bfloat16* __restrict__ Ahi, const __nv_bfloat16* __restrict__ Alo,
    int lda, size_t a_zs,
    const __nv_bfloat16* __restrict__ Bhi, const __nv_bfloat16* __restrict__ Blo,
    int ldb, size_t b_zs,
    const float* __restrict__ bias,
    float* __restrict__ Cf,
    __nv_bfloat16* __restrict__ Chi, __nv_bfloat16* __restrict__ Clo,
    int ldc, size_t c_zs,
    int K, int flags)
{
    static_assert(NI % 2 == 0, "NI must be even for x4 B loads");
    constexpr int ROWS    = WGM * MI * 16;
    constexpr int NT      = WGN * NI * 8;
    constexpr int A_BYTES = ROWS * 128;
    constexpr int B_BYTES = NT * 128;
    constexpr int SB_HI   = 2 * A_BYTES;
    constexpr int SB_LO   = 2 * A_BYTES + B_BYTES;
    constexpr int STB     = 2 * A_BYTES + 2 * B_BYTES;
    constexpr int BS      = NT + 4;

    extern __shared__ char smem_raw[];
    uint32_t base0 = smem_u32(smem_raw);
    uint32_t base  = (base0 + 1023) & ~1023u;
    char*    smem  = smem_raw + (base - base0);

    const int tid  = threadIdx.x;
    const int warp = tid >> 5, lane = tid & 31;
    const int wm = warp / WGN, wn = warp % WGN;
    const int rowA0 = blockIdx.y * ROWS;
    const int rowB0 = blockIdx.x * NT;
    const size_t z = blockIdx.z;

    const __nv_bfloat16* AhiZ = Ahi + z * a_zs;
    const __nv_bfloat16* AloZ = Alo + z * a_zs;
    const __nv_bfloat16* BhiZ = Bhi + z * b_zs;
    const __nv_bfloat16* BloZ = Blo + z * b_zs;

    float acc[MI][NI][4];
    #pragma unroll
    for (int mi = 0; mi < MI; mi++)
        #pragma unroll
        for (int ni = 0; ni < NI; ni++)
            #pragma unroll
            for (int r = 0; r < 4; r++) acc[mi][ni][r] = 0.0f;

    const int nchunks = K >> 6;

    auto load_chunk = [&](int chunk, int stage) {
        const int k0 = chunk << 6;
        uint32_t st = base + stage * STB;
        #pragma unroll
        for (int l = 0; l < ROWS * 8 / 256; l++) {
            int id = tid + (l << 8);
            int r = id >> 3, c = id & 7;
            uint32_t so = SW128((uint32_t)(r * 128 + c * 16));
            size_t ga = (size_t)(rowA0 + r) * lda + k0 + (c << 3);
            cp_async16(st + so, AhiZ + ga);
            cp_async16(st + A_BYTES + so, AloZ + ga);
        }
        #pragma unroll
        for (int l = 0; l < NT * 8 / 256; l++) {
            int id = tid + (l << 8);
            int r = id >> 3, c = id & 7;
            uint32_t so = SW128((uint32_t)(r * 128 + c * 16));
            size_t gb = (size_t)(rowB0 + r) * ldb + k0 + (c << 3);
            cp_async16(st + SB_HI + so, BhiZ + gb);
            cp_async16(st + SB_LO + so, BloZ + gb);
        }
        asm volatile("cp.async.commit_group;");
    };

    const int a_row_l = wm * (MI * 16) + (lane & 15);
    const int a_cb_l  = (lane >> 4) << 4;
    const int b_row_l = wn * (NI * 8) + (lane & 7) + ((lane >> 4) << 3);
    const int b_cb_l  = ((lane >> 3) & 1) << 4;

    load_chunk(0, 0);

    for (int i = 0; i < nchunks; i++) {
        const int s = i & 1;
        if (i + 1 < nchunks) {
            load_chunk(i + 1, 1 - s);
            asm volatile("cp.async.wait_group 1;");
        } else {
            asm volatile("cp.async.wait_group 0;");
        }
        __syncthreads();

        const uint32_t st = base + s * STB;
        #pragma unroll
        for (int ks = 0; ks < 4; ks++) {
            const int kb = ks << 5;
            uint32_t ah[MI][4], al[MI][4], bh[NI][2], bl[NI][2];
            #pragma unroll
            for (int mi = 0; mi < MI; mi++) {
                uint32_t so = SW128((uint32_t)((a_row_l + mi * 16) * 128 + kb + a_cb_l));
                ldsm_x4(ah[mi][0], ah[mi][1], ah[mi][2], ah[mi][3], st + so);
                ldsm_x4(al[mi][0], al[mi][1], al[mi][2], al[mi][3], st + A_BYTES + so);
            }
            #pragma unroll
            for (int p = 0; p < NI / 2; p++) {
                uint32_t off = SW128((uint32_t)((b_row_l + p * 16) * 128 + kb + b_cb_l));
                ldsm_x4(bh[2 * p][0], bh[2 * p][1], bh[2 * p + 1][0], bh[2 * p + 1][1],
                        st + SB_HI + off);
                ldsm_x4(bl[2 * p][0], bl[2 * p][1], bl[2 * p + 1][0], bl[2 * p + 1][1],
                        st + SB_LO + off);
            }
            #pragma unroll
            for (int ni = 0; ni < NI; ni++)
                #pragma unroll
                for (int mi = 0; mi < MI; mi++) {
                    mma16816(acc[mi][ni], ah[mi], bh[ni][0], bh[ni][1]);
                    mma16816(acc[mi][ni], ah[mi], bl[ni][0], bl[ni][1]);
                    mma16816(acc[mi][ni], al[mi], bh[ni][0], bh[ni][1]);
                }
        }
        __syncthreads();
    }

    // ---- epilogue: regs -> SMEM bounce (stride BS f32) -> global
    float* buf = (float*)smem;
    {
        const int r0 = wm * (MI * 16) + (lane >> 2);
        const int c0 = wn * (NI * 8) + ((lane & 3) << 1);
        #pragma unroll
        for (int mi = 0; mi < MI; mi++)
            #pragma unroll
            for (int ni = 0; ni < NI; ni++) {
                int rr = r0 + mi * 16;
                int cc = c0 + ni * 8;
                buf[rr * BS + cc]           = acc[mi][ni][0];
                buf[rr * BS + cc + 1]       = acc[mi][ni][1];
                buf[(rr + 8) * BS + cc]     = acc[mi][ni][2];
                buf[(rr + 8) * BS + cc + 1] = acc[mi][ni][3];
            }
    }
    __syncthreads();

    {
        constexpr int TPR = 256 / ROWS;
        constexpr int CPT = NT / TPR;
        const int rloc = tid / TPR;
        const int colb = (tid % TPR) * CPT;
        const size_t grow = (size_t)(rowA0 + rloc);
        float vals[CPT];
        #pragma unroll
        for (int c = 0; c < CPT; c++) {
            float v = buf[rloc * BS + colb + c];
            if (bias) v += bias[rowB0 + colb + c];
            if (flags & FL_RELU) v = fmaxf(v, 0.0f);
            vals[c] = v;
        }
        if (flags & FL_F32) {
            float* crow = Cf + z * c_zs + grow * ldc + rowB0 + colb;
            #pragma unroll
            for (int c = 0; c < CPT; c += 4) {
                float4 o = {vals[c], vals[c + 1], vals[c + 2], vals[c + 3]};
                *(float4*)(crow + c) = o;
            }
        }
        if (flags & FL_SPLIT) {
            __nv_bfloat16* hrow = Chi + z * c_zs + grow * ldc + rowB0 + colb;
            __nv_bfloat16* lrow = Clo + z * c_zs + grow * ldc + rowB0 + colb;
            #pragma unroll
            for (int c = 0; c < CPT; c += 8) {
                __nv_bfloat16 hv[8], lv[8];
                #pragma unroll
                for (int u = 0; u < 8; u++) {
                    float v = vals[c + u];
                    hv[u] = __float2bfloat16(v);
                    lv[u] = __float2bfloat16(v - __bfloat162float(hv[u]));
                }
                *(uint4*)(hrow + c) = *(uint4*)hv;
                *(uint4*)(lrow + c) = *(uint4*)lv;
            }
        }
    }
}

// variants: BIG 128x128 (occ1), SLIM 128x64 (occ2)
#define TG_BIG  tgemm_kernel<2, 4, 4, 4, 1>
#define TG_SLIM tgemm_kernel<4, 2, 2, 4, 2>
#define SMEM_BIG  (1024 + 2 * (2 * 128 * 128 + 2 * 128 * 128))   // 132096
#define SMEM_SLIM (1024 + 2 * (2 * 128 * 128 + 2 * 64 * 128))    // 99328

// ---------------------------------------------------------------------------
// Fused attention v2 (R12): register-reuse logits + loop-swapped hbar.
// ---------------------------------------------------------------------------
#define HS 516
#define WS 516
#define QS 68
#define PS_ 132
#define SM_QV   0
#define SM_WT   (8 * QS)
#define SM_HID  (SM_WT + 8 * WS)
#define SM_VV   (SM_HID + 16 * HS)
#define SM_PART (SM_VV + 16 * 512)
#define AT_FLOATS (SM_PART + 16 * PS_ + 16)
#define AT_SMEM (AT_FLOATS * 4)

__global__ __launch_bounds__(256) void attn_fused_kernel(
    const float* __restrict__ qh, const float* __restrict__ kvb,
    const float* __restrict__ hidden, const float* __restrict__ wtilde,
    const void* __restrict__ idx_raw,
    __nv_bfloat16* __restrict__ aout_hi, __nv_bfloat16* __restrict__ aout_lo)
{
    extern __shared__ float sm[];
    float* qvp  = sm + SM_QV;
    float* wt   = sm + SM_WT;
    float* hid  = sm + SM_HID;
    float* vv   = sm + SM_VV;
    float* part = sm + SM_PART;
    __shared__ int   sidx[JJ];
    __shared__ float lg[JJ][HH];
    __shared__ __align__(16) float aw[JJ][HH];

    const int row = blockIdx.x;
    const int b   = row >> 11;
    const int t   = threadIdx.x;

    if (t < JJ) {
        long long n;
        if (g_idx_is64) n = ((const long long*)idx_raw)[(size_t)row * JJ + t];
        else            n = ((const int*)idx_raw)[(size_t)row * JJ + t];
        sidx[t] = b * NKK + (int)n;
    }
    #pragma unroll
    for (int rep = 0; rep < 2; rep++) {
        int o = t + (rep << 8);
        qvp[(o >> 6) * QS + (o & 63)] = qh[(size_t)row * 512 + o];
    }
    {
        const float4* wsrc = (const float4*)(wtilde + (size_t)row * 4096);
        #pragma unroll
        for (int l = 0; l < 4; l++) {
            int i4 = t + (l << 8);
            int h = i4 >> 7, c = (i4 & 127) << 2;
            *(float4*)(wt + h * WS + c) = wsrc[i4];
        }
        const float4* hsrc = (const float4*)(hidden + (size_t)row * JJ * 512);
        #pragma unroll
        for (int l = 0; l < 8; l++) {
            int i4 = t + (l << 8);
            int j = i4 >> 7, c = (i4 & 127) << 2;
            *(float4*)(hid + j * HS + c) = hsrc[i4];
        }
    }
    __syncthreads();
    #pragma unroll
    for (int j = 0; j < JJ; j++) {
        const float2* vp = (const float2*)(kvb + (size_t)sidx[j] * 1024 + 512);
        ((float2*)(vv + j * 512))[t] = vp[t];
    }

    // ---- logits partials
    {
        const int cb = t >> 4;
        const int j  = t & 15;
        float h32[32];
        const float* hrow = hid + j * HS + cb * 32;
        #pragma unroll
        for (int i = 0; i < 32; i += 4) {
            float4 v = *(const float4*)(hrow + i);
            h32[i] = v.x; h32[i + 1] = v.y; h32[i + 2] = v.z; h32[i + 3] = v.w;
        }
        const int stag = (cb & 1) << 4;
        #pragma unroll
        for (int h = 0; h < 8; h++) {
            const float* wrow = wt + h * WS + cb * 32;
            float p = 0.0f;
            #pragma unroll
            for (int ii = 0; ii < 32; ii++) {
                int i = (ii + stag) & 31;
                p = fmaf(h32[i], wrow[i], p);
            }
            part[cb * PS_ + j * 8 + h] = p;
        }
    }
    __syncthreads();

    // ---- reduce partials + q.k term
    if (t < JJ * HH) {
        const int j = t >> 3, h = t & 7;
        float s = 0.0f;
        #pragma unroll
        for (int cb = 0; cb < 16; cb++) s += part[cb * PS_ + j * 8 + h];
        const float* kp = kvb + (size_t)sidx[j] * 1024 + h * 64;
        const float* qp = qvp + h * QS;
        #pragma unroll
        for (int d = 0; d < 64; d += 4) {
            float4 k4 = *(const float4*)(kp + d);
            s = fmaf(qp[d + 0], k4.x, s);
            s = fmaf(qp[d + 1], k4.y, s);
            s = fmaf(qp[d + 2], k4.z, s);
            s = fmaf(qp[d + 3], k4.w, s);
        }
        lg[j][h] = s * 0.125f;
    }
    __syncthreads();

    if (t < HH) {
        float m = -1e30f;
        #pragma unroll
        for (int j = 0; j < JJ; j++) m = fmaxf(m, lg[j][t]);
        float ssum = 0.0f;
        #pragma unroll
        for (int j = 0; j < JJ; j++) {
            float e = expf(lg[j][t] - m);
            aw[j][t] = e;
            ssum += e;
        }
        float inv = 1.0f / ssum;
        #pragma unroll
        for (int j = 0; j < JJ; j++) aw[j][t] *= inv;
    }
    __syncthreads();

    // ---- akv
    #pragma unroll
    for (int rep = 0; rep < 2; rep++) {
        int o = t + (rep << 8);
        int h = o >> 6, d = o & 63;
        float a = 0.0f;
        #pragma unroll
        for (int j = 0; j < JJ; j++)
            a = fmaf(aw[j][h], vv[j * 512 + h * 64 + d], a);
        __nv_bfloat16 hv = __float2bfloat16(a);
        __nv_bfloat16 lv = __float2bfloat16(a - __bfloat162float(hv));
        aout_hi[(size_t)row * KCAT + o] = hv;
        aout_lo[(size_t)row * KCAT + o] = lv;
    }

    // ---- hbar loop-swapped
    {
        const int c0 = t << 1;
        float a2[8][2];
        #pragma unroll
        for (int h = 0; h < 8; h++) { a2[h][0] = 0.0f; a2[h][1] = 0.0f; }
        #pragma unroll
        for (int j = 0; j < JJ; j++) {
            float2 v = *(const float2*)(hid + j * HS + c0);
            float4 w0 = *(const float4*)(&aw[j][0]);
            float4 w1 = *(const float4*)(&aw[j][4]);
            a2[0][0] = fmaf(w0.x, v.x, a2[0][0]); a2[0][1] = fmaf(w0.x, v.y, a2[0][1]);
            a2[1][0] = fmaf(w0.y, v.x, a2[1][0]); a2[1][1] = fmaf(w0.y, v.y, a2[1][1]);
            a2[2][0] = fmaf(w0.z, v.x, a2[2][0]); a2[2][1] = fmaf(w0.z, v.y, a2[2][1]);
            a2[3][0] = fmaf(w0.w, v.x, a2[3][0]); a2[3][1] = fmaf(w0.w, v.y, a2[3][1]);
            a2[4][0] = fmaf(w1.x, v.x, a2[4][0]); a2[4][1] = fmaf(w1.x, v.y, a2[4][1]);
            a2[5][0] = fmaf(w1.y, v.x, a2[5][0]); a2[5][1] = fmaf(w1.y, v.y, a2[5][1]);
            a2[6][0] = fmaf(w1.z, v.x, a2[6][0]); a2[6][1] = fmaf(w1.z, v.y, a2[6][1]);
            a2[7][0] = fmaf(w1.w, v.x, a2[7][0]); a2[7][1] = fmaf(w1.w, v.y, a2[7][1]);
        }
        #pragma unroll
        for (int h = 0; h < 8; h++) {
            __nv_bfloat16 h0 = __float2bfloat16(a2[h][0]);
            __nv_bfloat16 h1 = __float2bfloat16(a2[h][1]);
            __nv_bfloat16 l0 = __float2bfloat16(a2[h][0] - __bfloat162float(h0));
            __nv_bfloat16 l1 = __float2bfloat16(a2[h][1] - __bfloat162float(h1));
            size_t ob = (size_t)row * KCAT + 512 + h * 512 + c0;
            *(__nv_bfloat162*)(aout_hi + ob) = __nv_bfloat162(h0, h1);
            *(__nv_bfloat162*)(aout_lo + ob) = __nv_bfloat162(l0, l1);
        }
    }
}

// ---------------------------------------------------------------------------
// Launch: R14 schedule + pos-split quarter pipeline on s3 (only change)
// inputs: 0:q 1:k 2:pos 3:local_idx 4:Wq 5:Wkv 6:W1 7:b1 8:W2 9:b2 10:Wout
// ---------------------------------------------------------------------------
extern "C" void kernel_launch(void* const* d_in, const int* in_sizes, int n_in,
                              void* d_out, int out_size)
{
    const float* q    = (const float*)d_in[0];
    const float* k    = (const float*)d_in[1];
    const float* pos  = (const float*)d_in[2];
    const void*  lidx = d_in[3];
    const float* Wq   = (const float*)d_in[4];
    const float* Wkv  = (const float*)d_in[5];
    const float* W1   = (const float*)d_in[6];
    const float* b1   = (const float*)d_in[7];
    const float* W2   = (const float*)d_in[8];
    const float* b2   = (const float*)d_in[9];
    const float* Wout = (const float*)d_in[10];
    float* out = (float*)d_out;

    static cudaStream_t s1 = nullptr, s2 = nullptr, s3 = nullptr;
    static cudaEvent_t ev0, ev1, ev2, evp[4];
    static int init_done = 0;
    if (!init_done) {
        cudaStreamCreateWithFlags(&s1, cudaStreamNonBlocking);
        cudaStreamCreateWithFlags(&s2, cudaStreamNonBlocking);
        cudaStreamCreateWithFlags(&s3, cudaStreamNonBlocking);
        cudaEventCreateWithFlags(&ev0, cudaEventDisableTiming);
        cudaEventCreateWithFlags(&ev1, cudaEventDisableTiming);
        cudaEventCreateWithFlags(&ev2, cudaEventDisableTiming);
        for (int i = 0; i < 4; i++)
            cudaEventCreateWithFlags(&evp[i], cudaEventDisableTiming);
        cudaFuncSetAttribute(TG_BIG,
                             cudaFuncAttributeMaxDynamicSharedMemorySize, SMEM_BIG);
        cudaFuncSetAttribute(TG_SLIM,
                             cudaFuncAttributeMaxDynamicSharedMemorySize, SMEM_SLIM);
        cudaFuncSetAttribute(attn_fused_kernel,
                             cudaFuncAttributeMaxDynamicSharedMemorySize, AT_SMEM);
        init_done = 1;
    }

    __nv_bfloat16 *qs_hi, *qs_lo, *ks_hi, *ks_lo, *ps_hi, *ps_lo;
    __nv_bfloat16 *qh2_hi, *qh2_lo, *w2s_hi, *w2s_lo;
    __nv_bfloat16 *aout_hi, *aout_lo, *wt_hi, *wt_lo, *wcat_hi, *wcat_lo;
    float *qh, *kv, *hidden, *wtilde, *wfold, *bfold;
    cudaGetSymbolAddress((void**)&qs_hi, g_qs_hi);
    cudaGetSymbolAddress((void**)&qs_lo, g_qs_lo);
    cudaGetSymbolAddress((void**)&ks_hi, g_ks_hi);
    cudaGetSymbolAddress((void**)&ks_lo, g_ks_lo);
    cudaGetSymbolAddress((void**)&ps_hi, g_ps_hi);
    cudaGetSymbolAddress((void**)&ps_lo, g_ps_lo);
    cudaGetSymbolAddress((void**)&qh2_hi, g_qh2_hi);
    cudaGetSymbolAddress((void**)&qh2_lo, g_qh2_lo);
    cudaGetSymbolAddress((void**)&w2s_hi, g_w2s_hi);
    cudaGetSymbolAddress((void**)&w2s_lo, g_w2s_lo);
    cudaGetSymbolAddress((void**)&aout_hi, g_aout_hi);
    cudaGetSymbolAddress((void**)&aout_lo, g_aout_lo);
    cudaGetSymbolAddress((void**)&wt_hi, g_wt_hi);
    cudaGetSymbolAddress((void**)&wt_lo, g_wt_lo);
    cudaGetSymbolAddress((void**)&wcat_hi, g_wcat_hi);
    cudaGetSymbolAddress((void**)&wcat_lo, g_wcat_lo);
    cudaGetSymbolAddress((void**)&qh,     g_qh);
    cudaGetSymbolAddress((void**)&kv,     g_kv);
    cudaGetSymbolAddress((void**)&hidden, g_hidden);
    cudaGetSymbolAddress((void**)&wtilde, g_wtilde);
    cudaGetSymbolAddress((void**)&wfold,  g_wfold);
    cudaGetSymbolAddress((void**)&bfold,  g_bfold);

    // fork
    detect_idx_kernel<<<1, 32>>>(lidx);
    cudaEventRecord(ev0, 0);
    cudaStreamWaitEvent(s1, ev0, 0);
    cudaStreamWaitEvent(s2, ev0, 0);
    cudaStreamWaitEvent(s3, ev0, 0);

    // ---- s3: pos split in 4 quarters (pipelined against W1 GEMM on s0)
    const size_t q_rows  = ROWS_BIJ / 4;            // 16384
    const size_t q_elems = q_rows * DHIDDEN;        // 8.4M
    for (int qt = 0; qt < 4; qt++) {
        size_t eoff = (size_t)qt * q_elems;
        size_t n4 = q_elems / 4;
        split_kernel<<<(unsigned)((n4 + 255) / 256), 256, 0, s3>>>(
            pos + eoff, ps_hi + eoff, ps_lo + eoff, n4);
        cudaEventRecord(evp[qt], s3);
    }

    // ---- s0 (critical path): W1T split, then W1 GEMM quarters
    splitT_kernel<<<(W1_SZ + 255) / 256, 256>>>(
        W1, wt_hi + W1_OFF, wt_lo + W1_OFF, DHIDDEN, DHIDDEN, DHIDDEN, 0);
    for (int qt = 0; qt < 4; qt++) {
        size_t eoff = (size_t)qt * q_elems;
        cudaStreamWaitEvent(0, evp[qt], 0);
        TG_SLIM<<<dim3(DHIDDEN / 64, q_rows / 128), 256, SMEM_SLIM>>>(
            ps_hi + eoff, ps_lo + eoff, DHIDDEN, 0,
            wt_hi + W1_OFF, wt_lo + W1_OFF, DHIDDEN, 0,
            b1, hidden + eoff, nullptr, nullptr, DHIDDEN, 0, DHIDDEN,
            FL_F32 | FL_RELU);
    }

    // ---- s1: q path + wtilde
    {
        size_t n4 = (size_t)ROWS_BI * DMODEL / 4;
        split_kernel<<<(unsigned)((n4 + 255) / 256), 256, 0, s1>>>(q, qs_hi, qs_lo, n4);
        splitT_kernel<<<(WQ_SZ + 255) / 256, 256, 0, s1>>>(
            Wq, wt_hi + WQ_OFF, wt_lo + WQ_OFF, DMODEL, DHIDDEN, DMODEL, 0);
        TG_BIG<<<dim3(4, 32, 1), 256, SMEM_BIG, s1>>>(
            qs_hi, qs_lo, DMODEL, 0,
            wt_hi + WQ_OFF, wt_lo + WQ_OFF, DMODEL, 0,
            nullptr, qh, qh2_hi, qh2_lo, DHIDDEN, 0, DMODEL, FL_F32 | FL_SPLIT);
        size_t w4 = (size_t)DHIDDEN * 2 * DHIDDEN / 4;
        split_kernel<<<(unsigned)((w4 + 255) / 256), 256, 0, s1>>>(W2, w2s_hi, w2s_lo, w4);
        TG_BIG<<<dim3(4, 32, 8), 256, SMEM_BIG, s1>>>(
            qh2_hi, qh2_lo, DHIDDEN, 64,
            w2s_hi, w2s_lo, 2 * DHIDDEN, 128,
            nullptr, wtilde, nullptr, nullptr, HH * DHIDDEN, 512, 64, FL_F32);
        cudaEventRecord(ev1, s1);
    }

    // ---- s2: k path + folded output weights
    {
        size_t n4 = (size_t)ROWS_BI * DMODEL / 4;
        split_kernel<<<(unsigned)((n4 + 255) / 256), 256, 0, s2>>>(k, ks_hi, ks_lo, n4);
        splitT_kernel<<<(WKV_SZ + 255) / 256, 256, 0, s2>>>(
            Wkv, wt_hi + WKV_OFF, wt_lo + WKV_OFF, DMODEL, 2 * DHIDDEN, DMODEL, 0);
        TG_BIG<<<dim3(8, 32, 1), 256, SMEM_BIG, s2>>>(
            ks_hi, ks_lo, DMODEL, 0,
            wt_hi + WKV_OFF, wt_lo + WKV_OFF, DMODEL, 0,
            nullptr, kv, nullptr, nullptr, 2 * DHIDDEN, 0, DMODEL, FL_F32);
        prep_fold_kernel<<<HH * DHIDDEN, 256, 0, s2>>>(W2, Wout, wfold);
        prep_bfold_kernel<<<1, 256, 0, s2>>>(b2, Wout, bfold);
        splitT_kernel<<<(DHIDDEN * DMODEL + 255) / 256, 256, 0, s2>>>(
            Wout, wcat_hi, wcat_lo, DHIDDEN, DMODEL, KCAT, 0);
        splitT_kernel<<<(HH * DHIDDEN * DMODEL + 255) / 256, 256, 0, s2>>>(
            wfold, wcat_hi, wcat_lo, HH * DHIDDEN, DMODEL, KCAT, DHIDDEN);
        cudaEventRecord(ev2, s2);
    }

    // join
    cudaStreamWaitEvent(0, ev1, 0);
    cudaStreamWaitEvent(0, ev2, 0);

    // fused attention -> combined [akv | hbar]
    attn_fused_kernel<<<ROWS_BI, 256, AT_SMEM>>>(
        qh, kv, hidden, wtilde, lidx, aout_hi, aout_lo);

    // out = aout @ [Wout; Wfold]^T + bfold : M=4096, N=256, K=4608 (SLIM)
    TG_SLIM<<<dim3(DMODEL / 64, ROWS_BI / 128), 256, SMEM_SLIM>>>(
        aout_hi, aout_lo, KCAT, 0,
        wcat_hi, wcat_lo, KCAT, 0,
        bfold, out, nullptr, nullptr, DMODEL, 0, KCAT, FL_F32);
}